// round 4
// baseline (speedup 1.0000x reference)
#include <cuda_runtime.h>

// Shapes (fixed by the problem)
#define B_   64
#define N_   64
#define FIN  64
#define HID  256
#define OUT  64
#define T_   4
#define E_   4032   // N*(N-1)

// Scratch (device globals: no allocation allowed)
__device__ float g_Pa[T_ * B_ * N_ * HID];   // x @ w1[:, :64, :]              (16 MB)
__device__ float g_Pb[T_ * B_ * N_ * HID];   // x @ w1[:, 64:, :] + b1         (16 MB)
__device__ float g_agg[B_ * N_ * OUT];       // edge2node aggregate            (1 MB)

// ---------- packed f32x2 helpers (sm_103a: 2x fp32 FMA throughput) ----------
__device__ __forceinline__ unsigned long long ffma2(unsigned long long a,
                                                    unsigned long long b,
                                                    unsigned long long c) {
    unsigned long long d;
    asm("fma.rn.f32x2 %0, %1, %2, %3;" : "=l"(d) : "l"(a), "l"(b), "l"(c));
    return d;
}
__device__ __forceinline__ unsigned long long dup2(float a) {
    unsigned long long d;
    asm("mov.b64 %0, {%1, %1};" : "=l"(d) : "f"(a));
    return d;
}
__device__ __forceinline__ float2 unpack2(unsigned long long v) {
    float2 r;
    asm("mov.b64 {%0, %1}, %2;" : "=f"(r.x), "=f"(r.y) : "l"(v));
    return r;
}

// ---------------------------------------------------------------------------
// K0: zero the aggregation buffer (graph replays must be deterministic)
// ---------------------------------------------------------------------------
__global__ void k_zero() {
    int i = blockIdx.x * 256 + threadIdx.x;   // grid = 1024 -> 262144 threads
    g_agg[i] = 0.f;
}

// ---------------------------------------------------------------------------
// K1: node projections.  X[4096,64] @ W_all[64,2048] where the 2048 cols are
// (type t, part p, hidden h):  p=0 -> Pa uses w1[t][k][h], p=1 -> Pb uses
// w1[t][64+k][h] (+ b1 folded into Pb).
// grid = (16 colblocks of 128, 64 rowblocks of 64), 256 threads.
// ---------------------------------------------------------------------------
__global__ void __launch_bounds__(256) k1_proj(const float* __restrict__ x,
                                               const float* __restrict__ w1,
                                               const float* __restrict__ b1) {
    __shared__ float sX[64 * 64];    // 16 KB
    __shared__ float sW[64 * 128];   // 32 KB  (total 48 KB)
    const int tid = threadIdx.x;
    const int rb = blockIdx.y, cb = blockIdx.x;

#pragma unroll
    for (int i = 0; i < 16; i++)
        sX[tid + i * 256] = x[rb * 4096 + tid + i * 256];

    const int colbase = cb * 128;
#pragma unroll
    for (int i = 0; i < 32; i++) {
        int idx = tid + i * 256;          // 8192 weight elems: [k][c]
        int k = idx >> 7, c = idx & 127;
        int col = colbase + c;
        int t = col >> 9, part = (col >> 8) & 1, h = col & 255;
        sW[idx] = w1[t * 32768 + (part * 64 + k) * 256 + h];
    }
    __syncthreads();

    const int to = tid & 31, tr = tid >> 5;   // 32 col-groups x 8 row-groups
    float acc[8][4];
#pragma unroll
    for (int r = 0; r < 8; r++)
#pragma unroll
        for (int j = 0; j < 4; j++) acc[r][j] = 0.f;

#pragma unroll 4
    for (int k = 0; k < 64; k++) {
        float4 w = *(const float4*)(sW + k * 128 + to * 4);
        float a[8];
#pragma unroll
        for (int r = 0; r < 8; r++) a[r] = sX[(tr * 8 + r) * 64 + k];
#pragma unroll
        for (int r = 0; r < 8; r++) {
            acc[r][0] += a[r] * w.x;
            acc[r][1] += a[r] * w.y;
            acc[r][2] += a[r] * w.z;
            acc[r][3] += a[r] * w.w;
        }
    }

    const int col0 = colbase + to * 4;
    const int t = col0 >> 9, part = (col0 >> 8) & 1, h = col0 & 255;
    float4 bias = make_float4(0.f, 0.f, 0.f, 0.f);
    if (part) {
        bias.x = b1[t * 256 + h + 0];
        bias.y = b1[t * 256 + h + 1];
        bias.z = b1[t * 256 + h + 2];
        bias.w = b1[t * 256 + h + 3];
    }
    float* dst = (part ? g_Pb : g_Pa) + (t * 4096 + rb * 64 + tr * 8) * 256 + h;
#pragma unroll
    for (int r = 0; r < 8; r++) {
        float4 v = make_float4(acc[r][0] + bias.x, acc[r][1] + bias.y,
                               acc[r][2] + bias.z, acc[r][3] + bias.w);
        *(float4*)(dst + r * 256) = v;
    }
}

// ---------------------------------------------------------------------------
// K2 (dominant): per (batch b, type t, receiver block of 4):
//   for each receiver r: build A[s][k] = relu(Pa[s][k] + Pb[r][k]) in SMEM,
//   GEMM 64x64x256 vs w2[t] with packed f32x2 FMAs, epilogue:
//   out[o] = sum_s relu(C[s][o] + b2[o]) * rel_type[b, e(s,r), t],
//   accumulated into g_agg via smem reduce + one global atomicAdd.
// grid = (16, T_, B_), 256 threads, 128.75 KB dynamic smem.
// ---------------------------------------------------------------------------
#define K2_SMEM ((16384 + 16384 + 64 + 64 + 64) * 4)

__global__ void __launch_bounds__(256) k2_edge(const float* __restrict__ rel_type,
                                               const float* __restrict__ w2,
                                               const float* __restrict__ b2) {
    extern __shared__ float sm[];
    float* sB = sm;                    // w2[t]  [k=256][o=64]
    float* sA = sm + 16384;            // h1     [s=64][k=256]
    float* rt_sm = sm + 32768;         // rel_type per sender (current r)
    float* outbuf = rt_sm + 64;        // per-r output accumulator
    float* b2s = outbuf + 64;          // b2[t]

    const int tid = threadIdx.x;
    const int b = blockIdx.z, t = blockIdx.y, rbase = blockIdx.x * 4;

    const float* w2t = w2 + t * 16384;
#pragma unroll 8
    for (int i = 0; i < 64; i++)
        sB[tid + i * 256] = w2t[tid + i * 256];
    if (tid < 64) b2s[tid] = b2[t * 64 + tid];

    const float* PaBase = g_Pa + (t * 4096 + b * 64) * 256;
    const float* PbBase = g_Pb + (t * 4096 + b * 64) * 256;
    const int to = tid & 15, ts = tid >> 4;

    for (int rr = 0; rr < 4; rr++) {
        const int r = rbase + rr;
        if (tid < 64) {
            float v = 0.f;
            if (tid != r) {
                int e = tid * 63 + r - (r > tid ? 1 : 0);
                v = rel_type[(b * 4032 + e) * 4 + t];
            }
            rt_sm[tid] = v;
            outbuf[tid] = 0.f;
        }
        // build h1 tile: thread owns column k=tid across all 64 senders
        const float pb = PbBase[r * 256 + tid];
#pragma unroll 8
        for (int s = 0; s < 64; s++)
            sA[s * 256 + tid] = fmaxf(PaBase[s * 256 + tid] + pb, 0.f);
        __syncthreads();

        // GEMM: thread computes senders ts*4..+3, outputs to*4..+3
        unsigned long long acc[4][2];
#pragma unroll
        for (int i = 0; i < 4; i++) { acc[i][0] = 0ull; acc[i][1] = 0ull; }

        const float* Abase = sA + (ts * 4) * 256;
#pragma unroll 4
        for (int k2 = 0; k2 < 128; k2++) {
            const float* bp = sB + (k2 * 2) * 64 + to * 4;
            unsigned long long bk0a = *(const unsigned long long*)(bp);
            unsigned long long bk0b = *(const unsigned long long*)(bp + 2);
            unsigned long long bk1a = *(const unsigned long long*)(bp + 64);
            unsigned long long bk1b = *(const unsigned long long*)(bp + 66);
#pragma unroll
            for (int i = 0; i < 4; i++) {
                float2 a = *(const float2*)(Abase + i * 256 + k2 * 2);
                unsigned long long ax = dup2(a.x);
                unsigned long long ay = dup2(a.y);
                acc[i][0] = ffma2(ax, bk0a, acc[i][0]);
                acc[i][1] = ffma2(ax, bk0b, acc[i][1]);
                acc[i][0] = ffma2(ay, bk1a, acc[i][0]);
                acc[i][1] = ffma2(ay, bk1b, acc[i][1]);
            }
        }
        __syncthreads();

        // epilogue: bias + relu + rel_type scale, reduce over this thread's senders
        float p0 = 0.f, p1 = 0.f, p2 = 0.f, p3 = 0.f;
        const float bb0 = b2s[to * 4 + 0], bb1 = b2s[to * 4 + 1];
        const float bb2 = b2s[to * 4 + 2], bb3 = b2s[to * 4 + 3];
#pragma unroll
        for (int i = 0; i < 4; i++) {
            float rt = rt_sm[ts * 4 + i];
            float2 c01 = unpack2(acc[i][0]);
            float2 c23 = unpack2(acc[i][1]);
            p0 += fmaxf(c01.x + bb0, 0.f) * rt;
            p1 += fmaxf(c01.y + bb1, 0.f) * rt;
            p2 += fmaxf(c23.x + bb2, 0.f) * rt;
            p3 += fmaxf(c23.y + bb3, 0.f) * rt;
        }
        atomicAdd(&outbuf[to * 4 + 0], p0);
        atomicAdd(&outbuf[to * 4 + 1], p1);
        atomicAdd(&outbuf[to * 4 + 2], p2);
        atomicAdd(&outbuf[to * 4 + 3], p3);
        __syncthreads();

        if (tid < 64)
            atomicAdd(&g_agg[(b * 64 + r) * 64 + tid], outbuf[tid]);
        __syncthreads();
    }
}

// ---------------------------------------------------------------------------
// K3: output MLP.  aug[4096,128] -> relu(@ow1) -> relu(@ow2) -> @ow3.
// grid = 256 blocks x 16 rows, 256 threads, 40 KB static smem.
// ---------------------------------------------------------------------------
__global__ void __launch_bounds__(256) k3_out(const float* __restrict__ x,
                                              const float* __restrict__ ow1,
                                              const float* __restrict__ ob1,
                                              const float* __restrict__ ow2,
                                              const float* __restrict__ ob2,
                                              const float* __restrict__ ow3,
                                              const float* __restrict__ ob3,
                                              float* __restrict__ out) {
    __shared__ float sAug[16 * 128];   // 8 KB
    __shared__ float sH[16 * 256];     // 16 KB
    __shared__ float sH2[16 * 256];    // 16 KB
    const int tid = threadIdx.x;
    const int base = blockIdx.x * 16;

#pragma unroll
    for (int i = 0; i < 8; i++) {
        int idx = tid + i * 256;             // 2048 elems
        int row = idx >> 7, c = idx & 127;
        float v = (c < 64) ? x[(base + row) * 64 + c]
                           : g_agg[(base + row) * 64 + (c - 64)];
        sAug[idx] = v;
    }
    __syncthreads();

    {   // stage 1: 128 -> 256
        float acc[16];
#pragma unroll
        for (int r = 0; r < 16; r++) acc[r] = 0.f;
        const int col = tid;
#pragma unroll 4
        for (int k = 0; k < 128; k++) {
            float w = ow1[k * 256 + col];
#pragma unroll
            for (int r = 0; r < 16; r++) acc[r] += sAug[r * 128 + k] * w;
        }
        float bb = ob1[col];
#pragma unroll
        for (int r = 0; r < 16; r++) sH[r * 256 + col] = fmaxf(acc[r] + bb, 0.f);
    }
    __syncthreads();

    {   // stage 2: 256 -> 256
        float acc[16];
#pragma unroll
        for (int r = 0; r < 16; r++) acc[r] = 0.f;
        const int col = tid;
#pragma unroll 4
        for (int k = 0; k < 256; k++) {
            float w = ow2[k * 256 + col];
#pragma unroll
            for (int r = 0; r < 16; r++) acc[r] += sH[r * 256 + k] * w;
        }
        float bb = ob2[col];
#pragma unroll
        for (int r = 0; r < 16; r++) sH2[r * 256 + col] = fmaxf(acc[r] + bb, 0.f);
    }
    __syncthreads();

    {   // stage 3: 256 -> 64
        const int col = tid & 63, rg = tid >> 6;   // 4 groups x 4 rows
        float acc[4] = {0.f, 0.f, 0.f, 0.f};
#pragma unroll 4
        for (int k = 0; k < 256; k++) {
            float w = ow3[k * 64 + col];
#pragma unroll
            for (int r = 0; r < 4; r++) acc[r] += sH2[(rg * 4 + r) * 256 + k] * w;
        }
        float bb = ob3[col];
#pragma unroll
        for (int r = 0; r < 4; r++)
            out[(base + rg * 4 + r) * 64 + col] = acc[r] + bb;
    }
}

// ---------------------------------------------------------------------------
extern "C" void kernel_launch(void* const* d_in, const int* in_sizes, int n_in,
                              void* d_out, int out_size) {
    const float* x        = (const float*)d_in[0];
    const float* rel_type = (const float*)d_in[1];
    // d_in[2]=rel_rec, d_in[3]=rel_send: structure is analytic, unused
    const float* w1  = (const float*)d_in[4];
    const float* b1  = (const float*)d_in[5];
    const float* w2  = (const float*)d_in[6];
    const float* b2  = (const float*)d_in[7];
    const float* ow1 = (const float*)d_in[8];
    const float* ob1 = (const float*)d_in[9];
    const float* ow2 = (const float*)d_in[10];
    const float* ob2 = (const float*)d_in[11];
    const float* ow3 = (const float*)d_in[12];
    const float* ob3 = (const float*)d_in[13];
    float* out = (float*)d_out;

    // Idempotent; first (non-captured) correctness call makes it stick.
    cudaFuncSetAttribute(k2_edge, cudaFuncAttributeMaxDynamicSharedMemorySize, K2_SMEM);

    k_zero<<<1024, 256>>>();
    k1_proj<<<dim3(16, 64), 256>>>(x, w1, b1);
    k2_edge<<<dim3(16, T_, B_), 256, K2_SMEM>>>(rel_type, w2, b2);
    k3_out<<<256, 256>>>(x, ow1, ob1, ow2, ob2, ow3, ob3, out);
}

// round 5
// speedup vs baseline: 3.1242x; 3.1242x over previous
#include <cuda_runtime.h>

// Shapes (fixed by the problem)
#define B_   64
#define N_   64
#define FIN  64
#define HID  256
#define OUT  64
#define T_   4
#define E_   4032   // N*(N-1)

typedef unsigned int u32;

// Scratch (device globals: no allocation allowed)
__device__ float g_Pa[T_ * B_ * N_ * HID];   // x @ w1[:, :64, :]
__device__ float g_Pb[T_ * B_ * N_ * HID];   // x @ w1[:, 64:, :] + b1
__device__ float g_agg[B_ * N_ * OUT];       // edge2node aggregate

// ---------------- tf32 helpers ----------------
__device__ __forceinline__ u32 f2tf32(float f) {
    u32 u;
    asm("cvt.rna.tf32.f32 %0, %1;" : "=r"(u) : "f"(f));
    return u;
}
__device__ __forceinline__ void mma_tf32(float c[4], const u32 a[4], const u32 b[2]) {
    asm volatile(
        "mma.sync.aligned.m16n8k8.row.col.f32.tf32.tf32.f32 "
        "{%0,%1,%2,%3}, {%4,%5,%6,%7}, {%8,%9}, {%0,%1,%2,%3};"
        : "+f"(c[0]), "+f"(c[1]), "+f"(c[2]), "+f"(c[3])
        : "r"(a[0]), "r"(a[1]), "r"(a[2]), "r"(a[3]), "r"(b[0]), "r"(b[1]));
}

// ---------------------------------------------------------------------------
// K1: node projections.  X[4096,64] @ W_all[64,2048]; cols = (t, part, h).
// part=0 -> Pa (w1[t][k][h]); part=1 -> Pb (w1[t][64+k][h] + b1).
// ---------------------------------------------------------------------------
__global__ void __launch_bounds__(256) k1_proj(const float* __restrict__ x,
                                               const float* __restrict__ w1,
                                               const float* __restrict__ b1) {
    __shared__ float sX[64 * 64];
    __shared__ float sW[64 * 128];
    const int tid = threadIdx.x;
    const int rb = blockIdx.y, cb = blockIdx.x;

#pragma unroll
    for (int i = 0; i < 16; i++)
        sX[tid + i * 256] = x[rb * 4096 + tid + i * 256];

    const int colbase = cb * 128;
#pragma unroll
    for (int i = 0; i < 32; i++) {
        int idx = tid + i * 256;
        int k = idx >> 7, c = idx & 127;
        int col = colbase + c;
        int t = col >> 9, part = (col >> 8) & 1, h = col & 255;
        sW[idx] = w1[t * 32768 + (part * 64 + k) * 256 + h];
    }
    __syncthreads();

    const int to = tid & 31, tr = tid >> 5;
    float acc[8][4];
#pragma unroll
    for (int r = 0; r < 8; r++)
#pragma unroll
        for (int j = 0; j < 4; j++) acc[r][j] = 0.f;

#pragma unroll 4
    for (int k = 0; k < 64; k++) {
        float4 w = *(const float4*)(sW + k * 128 + to * 4);
        float a[8];
#pragma unroll
        for (int r = 0; r < 8; r++) a[r] = sX[(tr * 8 + r) * 64 + k];
#pragma unroll
        for (int r = 0; r < 8; r++) {
            acc[r][0] += a[r] * w.x;
            acc[r][1] += a[r] * w.y;
            acc[r][2] += a[r] * w.z;
            acc[r][3] += a[r] * w.w;
        }
    }

    const int col0 = colbase + to * 4;
    const int t = col0 >> 9, part = (col0 >> 8) & 1, h = col0 & 255;
    float4 bias = make_float4(0.f, 0.f, 0.f, 0.f);
    if (part) {
        bias.x = b1[t * 256 + h + 0];
        bias.y = b1[t * 256 + h + 1];
        bias.z = b1[t * 256 + h + 2];
        bias.w = b1[t * 256 + h + 3];
    }
    float* dst = (part ? g_Pb : g_Pa) + (t * 4096 + rb * 64 + tr * 8) * 256 + h;
#pragma unroll
    for (int r = 0; r < 8; r++) {
        float4 v = make_float4(acc[r][0] + bias.x, acc[r][1] + bias.y,
                               acc[r][2] + bias.z, acc[r][3] + bias.w);
        *(float4*)(dst + r * 256) = v;
    }
}

// ---------------------------------------------------------------------------
// K2 (dominant, tensor-core): block = (b, 4 receivers). Loops t(4) x pair(2).
// sB = tf32(w2[t]) [k=256][o=64] pad 72; sA = tf32(relu(Pa[s]+Pb[r])) for 2
// stacked receivers [row=128][k=256] pad 260. mma.m16n8k8.tf32 GEMM 128x64x256.
// Epilogue: relu(C+b2)*rel_type, shuffle-reduce over senders, accumulate in
// smem outbuf across (t,pair); single plain global store per (b,r,o).
// ---------------------------------------------------------------------------
#define K2_SMEM ((256 * 72 + 128 * 260 + 256 + 128 + 64) * 4)

__global__ void __launch_bounds__(256) k2_edge(const float* __restrict__ rel_type,
                                               const float* __restrict__ w2,
                                               const float* __restrict__ b2) {
    extern __shared__ u32 smu[];
    u32* sBu = smu;                             // 256*72
    u32* sAu = smu + 256 * 72;                  // 128*260
    float* outbuf = (float*)(smu + 256 * 72 + 128 * 260);  // 256
    float* rt_sm = outbuf + 256;                // 128
    float* b2s = rt_sm + 128;                   // 64

    const int tid = threadIdx.x;
    const int lane = tid & 31, wid = tid >> 5;
    const int b = blockIdx.y, rbase = blockIdx.x * 4;

    outbuf[tid] = 0.f;

    const int mbase = (wid & 3) * 32;     // 32-row chunk (within 128 stacked rows)
    const int nbase = (wid >> 2) * 32;    // 32-col chunk (of 64 outputs)
    const int rr_warp = mbase >> 6;       // which of the 2 stacked receivers

    const int g4 = lane >> 2;             // groupID
    const int t4 = lane & 3;              // thread-in-group

    for (int t = 0; t < 4; t++) {
        __syncthreads();   // prior pair's mma done reading sBu
        // stage w2[t] -> sBu (tf32), [k][o] stride 72
        const float4* w2t4 = (const float4*)(w2 + t * 16384);
#pragma unroll
        for (int i = 0; i < 16; i++) {
            int idx = tid + i * 256;        // 4096 float4
            int k = idx >> 4, c4 = idx & 15;
            float4 w = w2t4[idx];
            u32* dst = sBu + k * 72 + c4 * 4;
            dst[0] = f2tf32(w.x); dst[1] = f2tf32(w.y);
            dst[2] = f2tf32(w.z); dst[3] = f2tf32(w.w);
        }
        if (tid < 64) b2s[tid] = b2[t * 64 + tid];

        const float4* Pa4 = (const float4*)(g_Pa + (t * 4096 + b * 64) * 256);
        const float4* Pb4 = (const float4*)(g_Pb + (t * 4096 + b * 64) * 256);

        for (int pair = 0; pair < 2; pair++) {
            __syncthreads();  // prior mma done reading sAu / epilogue done with rt_sm
            if (tid < 128) {
                int row = tid;
                int s = row & 63;
                int r = rbase + pair * 2 + (row >> 6);
                float v = 0.f;
                if (s != r) {
                    int e = s * 63 + r - (r > s ? 1 : 0);
                    v = rel_type[(b * 4032 + e) * 4 + t];
                }
                rt_sm[row] = v;
            }
            // build sA: row = rr*64 + s, tf32(relu(Pa[s] + Pb[r]))
#pragma unroll
            for (int i = 0; i < 32; i++) {
                int idx = tid + i * 256;      // 8192 float4
                int row = idx >> 6, c4 = idx & 63;
                int s = row & 63;
                int r = rbase + pair * 2 + (row >> 6);
                float4 pa = Pa4[s * 64 + c4];
                float4 pb = Pb4[r * 64 + c4];
                u32* dst = sAu + row * 260 + c4 * 4;
                dst[0] = f2tf32(fmaxf(pa.x + pb.x, 0.f));
                dst[1] = f2tf32(fmaxf(pa.y + pb.y, 0.f));
                dst[2] = f2tf32(fmaxf(pa.z + pb.z, 0.f));
                dst[3] = f2tf32(fmaxf(pa.w + pb.w, 0.f));
            }
            __syncthreads();

            // ---- 128x64x256 tf32 GEMM: warp does 32Mx32N via 2x4 m16n8k8 ----
            float c[8][4];
#pragma unroll
            for (int i = 0; i < 8; i++)
#pragma unroll
                for (int j = 0; j < 4; j++) c[i][j] = 0.f;

            const u32* Ab = sAu + (mbase + g4) * 260 + t4;
            const u32* Bb = sBu + t4 * 72 + nbase + g4;
#pragma unroll
            for (int kk = 0; kk < 32; kk++) {
                u32 a[2][4], bf[4][2];
#pragma unroll
                for (int mt = 0; mt < 2; mt++) {
                    const u32* p = Ab + mt * (16 * 260) + kk * 8;
                    a[mt][0] = p[0];
                    a[mt][1] = p[8 * 260];
                    a[mt][2] = p[4];
                    a[mt][3] = p[8 * 260 + 4];
                }
#pragma unroll
                for (int nt = 0; nt < 4; nt++) {
                    const u32* p = Bb + kk * (8 * 72) + nt * 8;
                    bf[nt][0] = p[0];
                    bf[nt][1] = p[4 * 72];
                }
#pragma unroll
                for (int mt = 0; mt < 2; mt++)
#pragma unroll
                    for (int nt = 0; nt < 4; nt++)
                        mma_tf32(c[mt * 4 + nt], a[mt], bf[nt]);
            }

            // ---- epilogue: relu(C+b2)*rt, reduce over senders ----
            float rtv[2][2];
#pragma unroll
            for (int mt = 0; mt < 2; mt++) {
                rtv[mt][0] = rt_sm[mbase + mt * 16 + g4];
                rtv[mt][1] = rt_sm[mbase + mt * 16 + g4 + 8];
            }
            const int recv_local = pair * 2 + rr_warp;
#pragma unroll
            for (int nt = 0; nt < 4; nt++) {
                int col0 = nbase + nt * 8 + 2 * t4;
                float bb0 = b2s[col0], bb1 = b2s[col0 + 1];
                float s0 = 0.f, s1 = 0.f;
#pragma unroll
                for (int mt = 0; mt < 2; mt++) {
                    s0 += fmaxf(c[mt * 4 + nt][0] + bb0, 0.f) * rtv[mt][0];
                    s1 += fmaxf(c[mt * 4 + nt][1] + bb1, 0.f) * rtv[mt][0];
                    s0 += fmaxf(c[mt * 4 + nt][2] + bb0, 0.f) * rtv[mt][1];
                    s1 += fmaxf(c[mt * 4 + nt][3] + bb1, 0.f) * rtv[mt][1];
                }
#pragma unroll
                for (int off = 4; off < 32; off <<= 1) {
                    s0 += __shfl_xor_sync(0xffffffffu, s0, off);
                    s1 += __shfl_xor_sync(0xffffffffu, s1, off);
                }
                if (g4 == 0) {   // lanes 0..3
                    atomicAdd(&outbuf[recv_local * 64 + col0], s0);
                    atomicAdd(&outbuf[recv_local * 64 + col0 + 1], s1);
                }
            }
        }
    }
    __syncthreads();
    {   // exclusive (b, r) ownership -> plain store, no global atomics
        int rl = tid >> 6, o = tid & 63;
        g_agg[(b * 64 + rbase + rl) * 64 + o] = outbuf[tid];
    }
}

// ---------------------------------------------------------------------------
// K3: output MLP, float4 weight loads, 4 cols x 4 rows per thread.
// grid = 256 blocks x 16 rows, 256 threads.
// ---------------------------------------------------------------------------
__global__ void __launch_bounds__(256) k3_out(const float* __restrict__ x,
                                              const float* __restrict__ ow1,
                                              const float* __restrict__ ob1,
                                              const float* __restrict__ ow2,
                                              const float* __restrict__ ob2,
                                              const float* __restrict__ ow3,
                                              const float* __restrict__ ob3,
                                              float* __restrict__ out) {
    __shared__ float sAug[16 * 128];
    __shared__ float4 sH[16 * 64];
    __shared__ float4 sH2[16 * 64];
    const int tid = threadIdx.x;
    const int base = blockIdx.x * 16;

#pragma unroll
    for (int i = 0; i < 8; i++) {
        int idx = tid + i * 256;
        int row = idx >> 7, c = idx & 127;
        float v = (c < 64) ? x[(base + row) * 64 + c]
                           : g_agg[(base + row) * 64 + (c - 64)];
        sAug[idx] = v;
    }
    __syncthreads();

    const int cg = tid & 63, rg = tid >> 6;
    const float* sHf = (const float*)sH;
    const float* sH2f = (const float*)sH2;

    {   // stage 1: 128 -> 256
        float acc[4][4];
#pragma unroll
        for (int r = 0; r < 4; r++)
#pragma unroll
            for (int j = 0; j < 4; j++) acc[r][j] = 0.f;
#pragma unroll 4
        for (int k = 0; k < 128; k++) {
            float4 w = *((const float4*)(ow1 + k * 256) + cg);
#pragma unroll
            for (int r = 0; r < 4; r++) {
                float a = sAug[(rg * 4 + r) * 128 + k];
                acc[r][0] += a * w.x; acc[r][1] += a * w.y;
                acc[r][2] += a * w.z; acc[r][3] += a * w.w;
            }
        }
        float4 bb = *((const float4*)ob1 + cg);
#pragma unroll
        for (int r = 0; r < 4; r++)
            sH[(rg * 4 + r) * 64 + cg] = make_float4(
                fmaxf(acc[r][0] + bb.x, 0.f), fmaxf(acc[r][1] + bb.y, 0.f),
                fmaxf(acc[r][2] + bb.z, 0.f), fmaxf(acc[r][3] + bb.w, 0.f));
    }
    __syncthreads();

    {   // stage 2: 256 -> 256
        float acc[4][4];
#pragma unroll
        for (int r = 0; r < 4; r++)
#pragma unroll
            for (int j = 0; j < 4; j++) acc[r][j] = 0.f;
#pragma unroll 4
        for (int k = 0; k < 256; k++) {
            float4 w = *((const float4*)(ow2 + k * 256) + cg);
#pragma unroll
            for (int r = 0; r < 4; r++) {
                float a = sHf[(rg * 4 + r) * 256 + k];
                acc[r][0] += a * w.x; acc[r][1] += a * w.y;
                acc[r][2] += a * w.z; acc[r][3] += a * w.w;
            }
        }
        float4 bb = *((const float4*)ob2 + cg);
#pragma unroll
        for (int r = 0; r < 4; r++)
            sH2[(rg * 4 + r) * 64 + cg] = make_float4(
                fmaxf(acc[r][0] + bb.x, 0.f), fmaxf(acc[r][1] + bb.y, 0.f),
                fmaxf(acc[r][2] + bb.z, 0.f), fmaxf(acc[r][3] + bb.w, 0.f));
    }
    __syncthreads();

    {   // stage 3: 256 -> 64
        const int cg2 = tid & 15, rg2 = tid >> 4;   // 16 colgroups x 16 rows
        float a0 = 0.f, a1 = 0.f, a2 = 0.f, a3 = 0.f;
#pragma unroll 4
        for (int k = 0; k < 256; k++) {
            float4 w = *((const float4*)(ow3 + k * 64) + cg2);
            float a = sH2f[rg2 * 256 + k];
            a0 += a * w.x; a1 += a * w.y; a2 += a * w.z; a3 += a * w.w;
        }
        float4 bb = *((const float4*)ob3 + cg2);
        float4 v = make_float4(a0 + bb.x, a1 + bb.y, a2 + bb.z, a3 + bb.w);
        *((float4*)(out + (base + rg2) * 64) + cg2) = v;
    }
}

// ---------------------------------------------------------------------------
extern "C" void kernel_launch(void* const* d_in, const int* in_sizes, int n_in,
                              void* d_out, int out_size) {
    const float* x        = (const float*)d_in[0];
    const float* rel_type = (const float*)d_in[1];
    // d_in[2]=rel_rec, d_in[3]=rel_send: structure is analytic, unused
    const float* w1  = (const float*)d_in[4];
    const float* b1  = (const float*)d_in[5];
    const float* w2  = (const float*)d_in[6];
    const float* b2  = (const float*)d_in[7];
    const float* ow1 = (const float*)d_in[8];
    const float* ob1 = (const float*)d_in[9];
    const float* ow2 = (const float*)d_in[10];
    const float* ob2 = (const float*)d_in[11];
    const float* ow3 = (const float*)d_in[12];
    const float* ob3 = (const float*)d_in[13];
    float* out = (float*)d_out;

    cudaFuncSetAttribute(k2_edge, cudaFuncAttributeMaxDynamicSharedMemorySize, K2_SMEM);

    k1_proj<<<dim3(16, 64), 256>>>(x, w1, b1);
    k2_edge<<<dim3(16, 64), 256, K2_SMEM>>>(rel_type, w2, b2);
    k3_out<<<256, 256>>>(x, ow1, ob1, ow2, ob2, ow3, ob3, out);
}

// round 6
// speedup vs baseline: 3.1279x; 1.0012x over previous
#include <cuda_runtime.h>

// Shapes (fixed by the problem)
#define B_   64
#define N_   64
#define FIN  64
#define HID  256
#define OUT  64
#define T_   4
#define E_   4032   // N*(N-1)

typedef unsigned int u32;

// Scratch (device globals: no allocation allowed)
__device__ float g_Pa[T_ * B_ * N_ * HID];   // x @ w1[:, :64, :]
__device__ float g_Pb[T_ * B_ * N_ * HID];   // x @ w1[:, 64:, :] + b1
__device__ float g_agg[B_ * N_ * OUT];       // edge2node aggregate

// ---------------- tf32 helpers ----------------
__device__ __forceinline__ u32 f2tf32(float f) {
    u32 u;
    asm("cvt.rna.tf32.f32 %0, %1;" : "=r"(u) : "f"(f));
    return u;
}
__device__ __forceinline__ void mma_tf32(float c[4], const u32 a[4], const u32 b[2]) {
    asm volatile(
        "mma.sync.aligned.m16n8k8.row.col.f32.tf32.tf32.f32 "
        "{%0,%1,%2,%3}, {%4,%5,%6,%7}, {%8,%9}, {%0,%1,%2,%3};"
        : "+f"(c[0]), "+f"(c[1]), "+f"(c[2]), "+f"(c[3])
        : "r"(a[0]), "r"(a[1]), "r"(a[2]), "r"(a[3]), "r"(b[0]), "r"(b[1]));
}

// ---------------------------------------------------------------------------
// K1: node projections.  X[4096,64] @ W_all[64,2048]; cols = (t, part, h).
// part=0 -> Pa (w1[t][k][h]); part=1 -> Pb (w1[t][64+k][h] + b1).
// ---------------------------------------------------------------------------
__global__ void __launch_bounds__(256) k1_proj(const float* __restrict__ x,
                                               const float* __restrict__ w1,
                                               const float* __restrict__ b1) {
    __shared__ float sX[64 * 64];
    __shared__ float sW[64 * 128];
    const int tid = threadIdx.x;
    const int rb = blockIdx.y, cb = blockIdx.x;

#pragma unroll
    for (int i = 0; i < 16; i++)
        sX[tid + i * 256] = x[rb * 4096 + tid + i * 256];

    const int colbase = cb * 128;
#pragma unroll
    for (int i = 0; i < 32; i++) {
        int idx = tid + i * 256;
        int k = idx >> 7, c = idx & 127;
        int col = colbase + c;
        int t = col >> 9, part = (col >> 8) & 1, h = col & 255;
        sW[idx] = w1[t * 32768 + (part * 64 + k) * 256 + h];
    }
    __syncthreads();

    const int to = tid & 31, tr = tid >> 5;
    float acc[8][4];
#pragma unroll
    for (int r = 0; r < 8; r++)
#pragma unroll
        for (int j = 0; j < 4; j++) acc[r][j] = 0.f;

#pragma unroll 4
    for (int k = 0; k < 64; k++) {
        float4 w = *(const float4*)(sW + k * 128 + to * 4);
        float a[8];
#pragma unroll
        for (int r = 0; r < 8; r++) a[r] = sX[(tr * 8 + r) * 64 + k];
#pragma unroll
        for (int r = 0; r < 8; r++) {
            acc[r][0] += a[r] * w.x;
            acc[r][1] += a[r] * w.y;
            acc[r][2] += a[r] * w.z;
            acc[r][3] += a[r] * w.w;
        }
    }

    const int col0 = colbase + to * 4;
    const int t = col0 >> 9, part = (col0 >> 8) & 1, h = col0 & 255;
    float4 bias = make_float4(0.f, 0.f, 0.f, 0.f);
    if (part) {
        bias.x = b1[t * 256 + h + 0];
        bias.y = b1[t * 256 + h + 1];
        bias.z = b1[t * 256 + h + 2];
        bias.w = b1[t * 256 + h + 3];
    }
    float* dst = (part ? g_Pb : g_Pa) + (t * 4096 + rb * 64 + tr * 8) * 256 + h;
#pragma unroll
    for (int r = 0; r < 8; r++) {
        float4 v = make_float4(acc[r][0] + bias.x, acc[r][1] + bias.y,
                               acc[r][2] + bias.z, acc[r][3] + bias.w);
        *(float4*)(dst + r * 256) = v;
    }
}

// ---------------------------------------------------------------------------
// K2 (dominant, tensor-core): block = (b, 4 receivers). Loops t(4) x pair(2).
// sB = tf32(w2[t]) [k=256][o=64] pad 72; sA = tf32(relu(Pa[s]+Pb[r])) for 2
// stacked receivers [row=128][k=256] pad 260. mma.m16n8k8.tf32 GEMM 128x64x256.
// Epilogue: relu(C+b2)*rel_type, shuffle-reduce over senders, accumulate in
// smem outbuf across (t,pair); single plain global store per (b,r,o).
// ---------------------------------------------------------------------------
#define K2_SMEM ((256 * 72 + 128 * 260 + 256 + 128 + 64) * 4)

__global__ void __launch_bounds__(256) k2_edge(const float* __restrict__ rel_type,
                                               const float* __restrict__ w2,
                                               const float* __restrict__ b2) {
    extern __shared__ u32 smu[];
    u32* sBu = smu;                             // 256*72
    u32* sAu = smu + 256 * 72;                  // 128*260
    float* outbuf = (float*)(smu + 256 * 72 + 128 * 260);  // 256
    float* rt_sm = outbuf + 256;                // 128
    float* b2s = rt_sm + 128;                   // 64

    const int tid = threadIdx.x;
    const int lane = tid & 31, wid = tid >> 5;
    const int b = blockIdx.y, rbase = blockIdx.x * 4;

    outbuf[tid] = 0.f;

    const int mbase = (wid & 3) * 32;     // 32-row chunk (within 128 stacked rows)
    const int nbase = (wid >> 2) * 32;    // 32-col chunk (of 64 outputs)
    const int rr_warp = mbase >> 6;       // which of the 2 stacked receivers

    const int g4 = lane >> 2;             // groupID
    const int t4 = lane & 3;              // thread-in-group

    for (int t = 0; t < 4; t++) {
        __syncthreads();   // prior pair's mma done reading sBu
        // stage w2[t] -> sBu (tf32), [k][o] stride 72
        const float4* w2t4 = (const float4*)(w2 + t * 16384);
#pragma unroll
        for (int i = 0; i < 16; i++) {
            int idx = tid + i * 256;        // 4096 float4
            int k = idx >> 4, c4 = idx & 15;
            float4 w = w2t4[idx];
            u32* dst = sBu + k * 72 + c4 * 4;
            dst[0] = f2tf32(w.x); dst[1] = f2tf32(w.y);
            dst[2] = f2tf32(w.z); dst[3] = f2tf32(w.w);
        }
        if (tid < 64) b2s[tid] = b2[t * 64 + tid];

        const float4* Pa4 = (const float4*)(g_Pa + (t * 4096 + b * 64) * 256);
        const float4* Pb4 = (const float4*)(g_Pb + (t * 4096 + b * 64) * 256);

        for (int pair = 0; pair < 2; pair++) {
            __syncthreads();  // prior mma done reading sAu / epilogue done with rt_sm
            if (tid < 128) {
                int row = tid;
                int s = row & 63;
                int r = rbase + pair * 2 + (row >> 6);
                float v = 0.f;
                if (s != r) {
                    int e = s * 63 + r - (r > s ? 1 : 0);
                    v = rel_type[(b * 4032 + e) * 4 + t];
                }
                rt_sm[row] = v;
            }
            // build sA: row = rr*64 + s, tf32(relu(Pa[s] + Pb[r]))
#pragma unroll
            for (int i = 0; i < 32; i++) {
                int idx = tid + i * 256;      // 8192 float4
                int row = idx >> 6, c4 = idx & 63;
                int s = row & 63;
                int r = rbase + pair * 2 + (row >> 6);
                float4 pa = Pa4[s * 64 + c4];
                float4 pb = Pb4[r * 64 + c4];
                u32* dst = sAu + row * 260 + c4 * 4;
                dst[0] = f2tf32(fmaxf(pa.x + pb.x, 0.f));
                dst[1] = f2tf32(fmaxf(pa.y + pb.y, 0.f));
                dst[2] = f2tf32(fmaxf(pa.z + pb.z, 0.f));
                dst[3] = f2tf32(fmaxf(pa.w + pb.w, 0.f));
            }
            __syncthreads();

            // ---- 128x64x256 tf32 GEMM: warp does 32Mx32N via 2x4 m16n8k8 ----
            float c[8][4];
#pragma unroll
            for (int i = 0; i < 8; i++)
#pragma unroll
                for (int j = 0; j < 4; j++) c[i][j] = 0.f;

            const u32* Ab = sAu + (mbase + g4) * 260 + t4;
            const u32* Bb = sBu + t4 * 72 + nbase + g4;
#pragma unroll
            for (int kk = 0; kk < 32; kk++) {
                u32 a[2][4], bf[4][2];
#pragma unroll
                for (int mt = 0; mt < 2; mt++) {
                    const u32* p = Ab + mt * (16 * 260) + kk * 8;
                    a[mt][0] = p[0];
                    a[mt][1] = p[8 * 260];
                    a[mt][2] = p[4];
                    a[mt][3] = p[8 * 260 + 4];
                }
#pragma unroll
                for (int nt = 0; nt < 4; nt++) {
                    const u32* p = Bb + kk * (8 * 72) + nt * 8;
                    bf[nt][0] = p[0];
                    bf[nt][1] = p[4 * 72];
                }
#pragma unroll
                for (int mt = 0; mt < 2; mt++)
#pragma unroll
                    for (int nt = 0; nt < 4; nt++)
                        mma_tf32(c[mt * 4 + nt], a[mt], bf[nt]);
            }

            // ---- epilogue: relu(C+b2)*rt, reduce over senders ----
            float rtv[2][2];
#pragma unroll
            for (int mt = 0; mt < 2; mt++) {
                rtv[mt][0] = rt_sm[mbase + mt * 16 + g4];
                rtv[mt][1] = rt_sm[mbase + mt * 16 + g4 + 8];
            }
            const int recv_local = pair * 2 + rr_warp;
#pragma unroll
            for (int nt = 0; nt < 4; nt++) {
                int col0 = nbase + nt * 8 + 2 * t4;
                float bb0 = b2s[col0], bb1 = b2s[col0 + 1];
                float s0 = 0.f, s1 = 0.f;
#pragma unroll
                for (int mt = 0; mt < 2; mt++) {
                    s0 += fmaxf(c[mt * 4 + nt][0] + bb0, 0.f) * rtv[mt][0];
                    s1 += fmaxf(c[mt * 4 + nt][1] + bb1, 0.f) * rtv[mt][0];
                    s0 += fmaxf(c[mt * 4 + nt][2] + bb0, 0.f) * rtv[mt][1];
                    s1 += fmaxf(c[mt * 4 + nt][3] + bb1, 0.f) * rtv[mt][1];
                }
#pragma unroll
                for (int off = 4; off < 32; off <<= 1) {
                    s0 += __shfl_xor_sync(0xffffffffu, s0, off);
                    s1 += __shfl_xor_sync(0xffffffffu, s1, off);
                }
                if (g4 == 0) {   // lanes 0..3
                    atomicAdd(&outbuf[recv_local * 64 + col0], s0);
                    atomicAdd(&outbuf[recv_local * 64 + col0 + 1], s1);
                }
            }
        }
    }
    __syncthreads();
    {   // exclusive (b, r) ownership -> plain store, no global atomics
        int rl = tid >> 6, o = tid & 63;
        g_agg[(b * 64 + rbase + rl) * 64 + o] = outbuf[tid];
    }
}

// ---------------------------------------------------------------------------
// K3: output MLP, float4 weight loads, 4 cols x 4 rows per thread.
// grid = 256 blocks x 16 rows, 256 threads.
// ---------------------------------------------------------------------------
__global__ void __launch_bounds__(256) k3_out(const float* __restrict__ x,
                                              const float* __restrict__ ow1,
                                              const float* __restrict__ ob1,
                                              const float* __restrict__ ow2,
                                              const float* __restrict__ ob2,
                                              const float* __restrict__ ow3,
                                              const float* __restrict__ ob3,
                                              float* __restrict__ out) {
    __shared__ float sAug[16 * 128];
    __shared__ float4 sH[16 * 64];
    __shared__ float4 sH2[16 * 64];
    const int tid = threadIdx.x;
    const int base = blockIdx.x * 16;

#pragma unroll
    for (int i = 0; i < 8; i++) {
        int idx = tid + i * 256;
        int row = idx >> 7, c = idx & 127;
        float v = (c < 64) ? x[(base + row) * 64 + c]
                           : g_agg[(base + row) * 64 + (c - 64)];
        sAug[idx] = v;
    }
    __syncthreads();

    const int cg = tid & 63, rg = tid >> 6;
    const float* sHf = (const float*)sH;
    const float* sH2f = (const float*)sH2;

    {   // stage 1: 128 -> 256
        float acc[4][4];
#pragma unroll
        for (int r = 0; r < 4; r++)
#pragma unroll
            for (int j = 0; j < 4; j++) acc[r][j] = 0.f;
#pragma unroll 4
        for (int k = 0; k < 128; k++) {
            float4 w = *((const float4*)(ow1 + k * 256) + cg);
#pragma unroll
            for (int r = 0; r < 4; r++) {
                float a = sAug[(rg * 4 + r) * 128 + k];
                acc[r][0] += a * w.x; acc[r][1] += a * w.y;
                acc[r][2] += a * w.z; acc[r][3] += a * w.w;
            }
        }
        float4 bb = *((const float4*)ob1 + cg);
#pragma unroll
        for (int r = 0; r < 4; r++)
            sH[(rg * 4 + r) * 64 + cg] = make_float4(
                fmaxf(acc[r][0] + bb.x, 0.f), fmaxf(acc[r][1] + bb.y, 0.f),
                fmaxf(acc[r][2] + bb.z, 0.f), fmaxf(acc[r][3] + bb.w, 0.f));
    }
    __syncthreads();

    {   // stage 2: 256 -> 256
        float acc[4][4];
#pragma unroll
        for (int r = 0; r < 4; r++)
#pragma unroll
            for (int j = 0; j < 4; j++) acc[r][j] = 0.f;
#pragma unroll 4
        for (int k = 0; k < 256; k++) {
            float4 w = *((const float4*)(ow2 + k * 256) + cg);
#pragma unroll
            for (int r = 0; r < 4; r++) {
                float a = sHf[(rg * 4 + r) * 256 + k];
                acc[r][0] += a * w.x; acc[r][1] += a * w.y;
                acc[r][2] += a * w.z; acc[r][3] += a * w.w;
            }
        }
        float4 bb = *((const float4*)ob2 + cg);
#pragma unroll
        for (int r = 0; r < 4; r++)
            sH2[(rg * 4 + r) * 64 + cg] = make_float4(
                fmaxf(acc[r][0] + bb.x, 0.f), fmaxf(acc[r][1] + bb.y, 0.f),
                fmaxf(acc[r][2] + bb.z, 0.f), fmaxf(acc[r][3] + bb.w, 0.f));
    }
    __syncthreads();

    {   // stage 3: 256 -> 64
        const int cg2 = tid & 15, rg2 = tid >> 4;   // 16 colgroups x 16 rows
        float a0 = 0.f, a1 = 0.f, a2 = 0.f, a3 = 0.f;
#pragma unroll 4
        for (int k = 0; k < 256; k++) {
            float4 w = *((const float4*)(ow3 + k * 64) + cg2);
            float a = sH2f[rg2 * 256 + k];
            a0 += a * w.x; a1 += a * w.y; a2 += a * w.z; a3 += a * w.w;
        }
        float4 bb = *((const float4*)ob3 + cg2);
        float4 v = make_float4(a0 + bb.x, a1 + bb.y, a2 + bb.z, a3 + bb.w);
        *((float4*)(out + (base + rg2) * 64) + cg2) = v;
    }
}

// ---------------------------------------------------------------------------
extern "C" void kernel_launch(void* const* d_in, const int* in_sizes, int n_in,
                              void* d_out, int out_size) {
    const float* x        = (const float*)d_in[0];
    const float* rel_type = (const float*)d_in[1];
    // d_in[2]=rel_rec, d_in[3]=rel_send: structure is analytic, unused
    const float* w1  = (const float*)d_in[4];
    const float* b1  = (const float*)d_in[5];
    const float* w2  = (const float*)d_in[6];
    const float* b2  = (const float*)d_in[7];
    const float* ow1 = (const float*)d_in[8];
    const float* ob1 = (const float*)d_in[9];
    const float* ow2 = (const float*)d_in[10];
    const float* ob2 = (const float*)d_in[11];
    const float* ow3 = (const float*)d_in[12];
    const float* ob3 = (const float*)d_in[13];
    float* out = (float*)d_out;

    cudaFuncSetAttribute(k2_edge, cudaFuncAttributeMaxDynamicSharedMemorySize, K2_SMEM);

    k1_proj<<<dim3(16, 64), 256>>>(x, w1, b1);
    k2_edge<<<dim3(16, 64), 256, K2_SMEM>>>(rel_type, w2, b2);
    k3_out<<<256, 256>>>(x, ow1, ob1, ow2, ob2, ow3, ob3, out);
}

// round 7
// speedup vs baseline: 6.0259x; 1.9265x over previous
#include <cuda_runtime.h>
#include <cuda_fp16.h>

// Shapes (fixed by the problem)
#define B_   64
#define N_   64
#define FIN  64
#define HID  256
#define OUT  64
#define T_   4
#define E_   4032   // N*(N-1)

typedef unsigned int u32;

// Scratch (device globals: no allocation allowed)
__device__ __half g_Pa[T_ * B_ * N_ * HID];   // x @ w1[:, :64, :]          (8 MB)
__device__ __half g_Pb[T_ * B_ * N_ * HID];   // x @ w1[:, 64:, :] + b1     (8 MB)
__device__ float  g_agg[B_ * N_ * OUT];       // edge2node aggregate        (1 MB)

// ---------------- fp16 mma helper ----------------
__device__ __forceinline__ void mma_f16(float c[4], const u32 a[4], const u32 b[2]) {
    asm volatile(
        "mma.sync.aligned.m16n8k16.row.col.f32.f16.f16.f32 "
        "{%0,%1,%2,%3},{%4,%5,%6,%7},{%8,%9},{%0,%1,%2,%3};"
        : "+f"(c[0]), "+f"(c[1]), "+f"(c[2]), "+f"(c[3])
        : "r"(a[0]), "r"(a[1]), "r"(a[2]), "r"(a[3]), "r"(b[0]), "r"(b[1]));
}

// ---------------------------------------------------------------------------
// K1: node projections.  X[4096,64] @ W_all[64,2048]; cols = (t, part, h).
// part=0 -> Pa (w1[t][k][h]); part=1 -> Pb (w1[t][64+k][h] + b1). fp16 out.
// ---------------------------------------------------------------------------
__global__ void __launch_bounds__(256) k1_proj(const float* __restrict__ x,
                                               const float* __restrict__ w1,
                                               const float* __restrict__ b1) {
    __shared__ float sX[64 * 64];
    __shared__ float sW[64 * 128];
    const int tid = threadIdx.x;
    const int rb = blockIdx.y, cb = blockIdx.x;

#pragma unroll
    for (int i = 0; i < 16; i++)
        sX[tid + i * 256] = x[rb * 4096 + tid + i * 256];

    const int colbase = cb * 128;
#pragma unroll
    for (int i = 0; i < 32; i++) {
        int idx = tid + i * 256;
        int k = idx >> 7, c = idx & 127;
        int col = colbase + c;
        int t = col >> 9, part = (col >> 8) & 1, h = col & 255;
        sW[idx] = w1[t * 32768 + (part * 64 + k) * 256 + h];
    }
    __syncthreads();

    const int to = tid & 31, tr = tid >> 5;
    float acc[8][4];
#pragma unroll
    for (int r = 0; r < 8; r++)
#pragma unroll
        for (int j = 0; j < 4; j++) acc[r][j] = 0.f;

#pragma unroll 4
    for (int k = 0; k < 64; k++) {
        float4 w = *(const float4*)(sW + k * 128 + to * 4);
        float a[8];
#pragma unroll
        for (int r = 0; r < 8; r++) a[r] = sX[(tr * 8 + r) * 64 + k];
#pragma unroll
        for (int r = 0; r < 8; r++) {
            acc[r][0] += a[r] * w.x;
            acc[r][1] += a[r] * w.y;
            acc[r][2] += a[r] * w.z;
            acc[r][3] += a[r] * w.w;
        }
    }

    const int col0 = colbase + to * 4;
    const int t = col0 >> 9, part = (col0 >> 8) & 1, h = col0 & 255;
    float4 bias = make_float4(0.f, 0.f, 0.f, 0.f);
    if (part) {
        bias.x = b1[t * 256 + h + 0];
        bias.y = b1[t * 256 + h + 1];
        bias.z = b1[t * 256 + h + 2];
        bias.w = b1[t * 256 + h + 3];
    }
    __half* dst = (part ? g_Pb : g_Pa) + ((t * 4096 + rb * 64 + tr * 8) * 256 + h);
#pragma unroll
    for (int r = 0; r < 8; r++) {
        __half2 h01 = __floats2half2_rn(acc[r][0] + bias.x, acc[r][1] + bias.y);
        __half2 h23 = __floats2half2_rn(acc[r][2] + bias.z, acc[r][3] + bias.w);
        uint2 v;
        v.x = *(u32*)&h01;
        v.y = *(u32*)&h23;
        *(uint2*)(dst + r * 256) = v;
    }
}

// ---------------------------------------------------------------------------
// K2 (dominant, fp16 tensor-core): block = (b, 4 receivers), loops t(4).
// sA [row=256(4 recv x 64 send)][k=256, pad 264] half = relu(Pa[s]+Pb[r]).
// sB [k=256][o=64, pad 72] half = w2[t].
// Warp (r_local = wid&3, nhalf = wid>>2): 64M x 32N x 256K via ldmatrix +
// mma.m16n8k16.f16.f32. Epilogue: relu(C+b2)*rel_type, shuffle-reduce over
// senders, accumulate in registers across t; one plain float2 store / lane.
// ---------------------------------------------------------------------------
#define SA_K 264
#define SB_O 72
#define K2_SMEM (256 * SA_K * 2 + 256 * SB_O * 2 + 256 * 4 + 64 * 4)

__global__ void __launch_bounds__(256) k2_edge(const float* __restrict__ rel_type,
                                               const float* __restrict__ w2,
                                               const float* __restrict__ b2) {
    extern __shared__ __align__(16) char smraw[];
    __half* sA = (__half*)smraw;                              // [256][SA_K]
    __half* sB = (__half*)(smraw + 256 * SA_K * 2);           // [256][SB_O]
    float* rt_sm = (float*)(smraw + 256 * SA_K * 2 + 256 * SB_O * 2);  // [4][64]
    float* b2s = rt_sm + 256;                                 // [64]

    const int tid = threadIdx.x;
    const int lane = tid & 31, wid = tid >> 5;
    const int b = blockIdx.y, rbase = blockIdx.x * 4;
    const int r_local = wid & 3;      // receiver owned by this warp
    const int nhalf = wid >> 2;       // which 32-col half of the 64 outputs
    const int g4 = lane >> 2, t4 = lane & 3;

    const u32 sA_u = (u32)__cvta_generic_to_shared(sA);
    const u32 sB_u = (u32)__cvta_generic_to_shared(sB);

    // ldmatrix lane address bases
    // A x4: m0 rows0-7/k0, m1 rows8-15/k0, m2 rows0-7/k8, m3 rows8-15/k8
    const u32 aAddr = sA_u +
        (u32)(((r_local * 64 + (lane & 7) + ((lane >> 3) & 1) * 8) * SA_K +
               (lane >> 4) * 8) * 2);
    // B x2.trans: lanes 0-15 -> rows k+0..15 (cols = nhalf*32 base)
    const u32 bAddr = sB_u + (u32)(((lane & 15) * SB_O + nhalf * 32) * 2);

    float racc[4][2];
#pragma unroll
    for (int nt = 0; nt < 4; nt++) { racc[nt][0] = 0.f; racc[nt][1] = 0.f; }

    const __half2 z2 = __float2half2_rn(0.f);

    for (int t = 0; t < 4; t++) {
        __syncthreads();   // previous iteration's mma/epilogue done

        // ---- stage sB = fp16(w2[t]) as [k][o] ----
        const float4* w2t4 = (const float4*)(w2 + t * 16384);
#pragma unroll
        for (int i = 0; i < 16; i++) {
            int idx = i * 256 + tid;            // 4096 float4
            int k = idx >> 4, o4 = idx & 15;
            float4 w = w2t4[idx];
            __half2 h01 = __floats2half2_rn(w.x, w.y);
            __half2 h23 = __floats2half2_rn(w.z, w.w);
            __half2* dst = (__half2*)(sB + k * SB_O + o4 * 4);
            dst[0] = h01;
            dst[1] = h23;
        }
        // ---- stage rel_type for 4 receivers x 64 senders ----
        {
            int s = tid & 63, rl = tid >> 6;
            int r = rbase + rl;
            float v = 0.f;
            if (s != r) v = rel_type[(b * 4032 + s * 63 + r - (r > s ? 1 : 0)) * 4 + t];
            rt_sm[rl * 64 + s] = v;
        }
        if (tid < 64) b2s[tid] = b2[t * 64 + tid];

        // ---- build sA: row = rl*64+s, relu(Pa[s] + Pb[rbase+rl]) in fp16 ----
        const __half* PaH = g_Pa + (t * 4096 + b * 64) * 256;
        const __half* PbH = g_Pb + (t * 4096 + b * 64) * 256;
#pragma unroll
        for (int i = 0; i < 32; i++) {
            int grp = i * 256 + tid;            // 8192 groups of 8 halves
            int row = grp >> 5, c8 = grp & 31;
            int s = row & 63, rl = row >> 6;
            uint4 pa = *(const uint4*)(PaH + s * 256 + c8 * 8);
            uint4 pb = *(const uint4*)(PbH + (rbase + rl) * 256 + c8 * 8);
            uint4 o;
            __half2 v;
            v = __hmax2(__hadd2(*(__half2*)&pa.x, *(__half2*)&pb.x), z2); o.x = *(u32*)&v;
            v = __hmax2(__hadd2(*(__half2*)&pa.y, *(__half2*)&pb.y), z2); o.y = *(u32*)&v;
            v = __hmax2(__hadd2(*(__half2*)&pa.z, *(__half2*)&pb.z), z2); o.z = *(u32*)&v;
            v = __hmax2(__hadd2(*(__half2*)&pa.w, *(__half2*)&pb.w), z2); o.w = *(u32*)&v;
            *(uint4*)(sA + row * SA_K + c8 * 8) = o;
        }
        __syncthreads();

        // ---- 64x32x256 warp GEMM: 4mt x 4nt m16n8k16 tiles, 16 k-chunks ----
        float c[16][4];
#pragma unroll
        for (int i = 0; i < 16; i++)
#pragma unroll
            for (int j = 0; j < 4; j++) c[i][j] = 0.f;

#pragma unroll
        for (int kc = 0; kc < 16; kc++) {
            u32 bf[4][2];
#pragma unroll
            for (int nt = 0; nt < 4; nt++) {
                u32 addr = bAddr + (u32)((kc * 16 * SB_O + nt * 8) * 2);
                asm volatile(
                    "ldmatrix.sync.aligned.m8n8.x2.trans.shared.b16 {%0,%1}, [%2];"
                    : "=r"(bf[nt][0]), "=r"(bf[nt][1]) : "r"(addr));
            }
#pragma unroll
            for (int mt = 0; mt < 4; mt++) {
                u32 a[4];
                u32 addr = aAddr + (u32)((mt * 16 * SA_K + kc * 16) * 2);
                asm volatile(
                    "ldmatrix.sync.aligned.m8n8.x4.shared.b16 {%0,%1,%2,%3}, [%4];"
                    : "=r"(a[0]), "=r"(a[1]), "=r"(a[2]), "=r"(a[3]) : "r"(addr));
#pragma unroll
                for (int nt = 0; nt < 4; nt++)
                    mma_f16(c[mt * 4 + nt], a, bf[nt]);
            }
        }

        // ---- epilogue: relu(C + b2)*rt, reduce over senders, accum in regs ----
        float rtv[4][2];
#pragma unroll
        for (int mt = 0; mt < 4; mt++) {
            rtv[mt][0] = rt_sm[r_local * 64 + mt * 16 + g4];
            rtv[mt][1] = rt_sm[r_local * 64 + mt * 16 + g4 + 8];
        }
#pragma unroll
        for (int nt = 0; nt < 4; nt++) {
            int col = nhalf * 32 + nt * 8 + 2 * t4;
            float bb0 = b2s[col], bb1 = b2s[col + 1];
            float p0 = 0.f, p1 = 0.f;
#pragma unroll
            for (int mt = 0; mt < 4; mt++) {
                const float* cc = c[mt * 4 + nt];
                p0 += fmaxf(cc[0] + bb0, 0.f) * rtv[mt][0];
                p1 += fmaxf(cc[1] + bb1, 0.f) * rtv[mt][0];
                p0 += fmaxf(cc[2] + bb0, 0.f) * rtv[mt][1];
                p1 += fmaxf(cc[3] + bb1, 0.f) * rtv[mt][1];
            }
#pragma unroll
            for (int off = 4; off < 32; off <<= 1) {
                p0 += __shfl_xor_sync(0xffffffffu, p0, off);
                p1 += __shfl_xor_sync(0xffffffffu, p1, off);
            }
            racc[nt][0] += p0;
            racc[nt][1] += p1;
        }
    }

    // ---- final store: each (b, r, col) owned by exactly one warp ----
    if (lane < 4) {   // g4 == 0 lanes, t4 = lane
        float* dst = g_agg + (b * 64 + rbase + r_local) * 64 + nhalf * 32 + 2 * t4;
#pragma unroll
        for (int nt = 0; nt < 4; nt++)
            *(float2*)(dst + nt * 8) = make_float2(racc[nt][0], racc[nt][1]);
    }
}

// ---------------------------------------------------------------------------
// K3: output MLP, float4 weight loads, 4 cols x 4 rows per thread.
// grid = 256 blocks x 16 rows, 256 threads.
// ---------------------------------------------------------------------------
__global__ void __launch_bounds__(256) k3_out(const float* __restrict__ x,
                                              const float* __restrict__ ow1,
                                              const float* __restrict__ ob1,
                                              const float* __restrict__ ow2,
                                              const float* __restrict__ ob2,
                                              const float* __restrict__ ow3,
                                              const float* __restrict__ ob3,
                                              float* __restrict__ out) {
    __shared__ float sAug[16 * 128];
    __shared__ float4 sH[16 * 64];
    __shared__ float4 sH2[16 * 64];
    const int tid = threadIdx.x;
    const int base = blockIdx.x * 16;

#pragma unroll
    for (int i = 0; i < 8; i++) {
        int idx = tid + i * 256;
        int row = idx >> 7, c = idx & 127;
        float v = (c < 64) ? x[(base + row) * 64 + c]
                           : g_agg[(base + row) * 64 + (c - 64)];
        sAug[idx] = v;
    }
    __syncthreads();

    const int cg = tid & 63, rg = tid >> 6;
    const float* sHf = (const float*)sH;
    const float* sH2f = (const float*)sH2;

    {   // stage 1: 128 -> 256
        float acc[4][4];
#pragma unroll
        for (int r = 0; r < 4; r++)
#pragma unroll
            for (int j = 0; j < 4; j++) acc[r][j] = 0.f;
#pragma unroll 4
        for (int k = 0; k < 128; k++) {
            float4 w = *((const float4*)(ow1 + k * 256) + cg);
#pragma unroll
            for (int r = 0; r < 4; r++) {
                float a = sAug[(rg * 4 + r) * 128 + k];
                acc[r][0] += a * w.x; acc[r][1] += a * w.y;
                acc[r][2] += a * w.z; acc[r][3] += a * w.w;
            }
        }
        float4 bb = *((const float4*)ob1 + cg);
#pragma unroll
        for (int r = 0; r < 4; r++)
            sH[(rg * 4 + r) * 64 + cg] = make_float4(
                fmaxf(acc[r][0] + bb.x, 0.f), fmaxf(acc[r][1] + bb.y, 0.f),
                fmaxf(acc[r][2] + bb.z, 0.f), fmaxf(acc[r][3] + bb.w, 0.f));
    }
    __syncthreads();

    {   // stage 2: 256 -> 256
        float acc[4][4];
#pragma unroll
        for (int r = 0; r < 4; r++)
#pragma unroll
            for (int j = 0; j < 4; j++) acc[r][j] = 0.f;
#pragma unroll 4
        for (int k = 0; k < 256; k++) {
            float4 w = *((const float4*)(ow2 + k * 256) + cg);
#pragma unroll
            for (int r = 0; r < 4; r++) {
                float a = sHf[(rg * 4 + r) * 256 + k];
                acc[r][0] += a * w.x; acc[r][1] += a * w.y;
                acc[r][2] += a * w.z; acc[r][3] += a * w.w;
            }
        }
        float4 bb = *((const float4*)ob2 + cg);
#pragma unroll
        for (int r = 0; r < 4; r++)
            sH2[(rg * 4 + r) * 64 + cg] = make_float4(
                fmaxf(acc[r][0] + bb.x, 0.f), fmaxf(acc[r][1] + bb.y, 0.f),
                fmaxf(acc[r][2] + bb.z, 0.f), fmaxf(acc[r][3] + bb.w, 0.f));
    }
    __syncthreads();

    {   // stage 3: 256 -> 64
        const int cg2 = tid & 15, rg2 = tid >> 4;
        float a0 = 0.f, a1 = 0.f, a2 = 0.f, a3 = 0.f;
#pragma unroll 4
        for (int k = 0; k < 256; k++) {
            float4 w = *((const float4*)(ow3 + k * 64) + cg2);
            float a = sH2f[rg2 * 256 + k];
            a0 += a * w.x; a1 += a * w.y; a2 += a * w.z; a3 += a * w.w;
        }
        float4 bb = *((const float4*)ob3 + cg2);
        float4 v = make_float4(a0 + bb.x, a1 + bb.y, a2 + bb.z, a3 + bb.w);
        *((float4*)(out + (base + rg2) * 64) + cg2) = v;
    }
}

// ---------------------------------------------------------------------------
extern "C" void kernel_launch(void* const* d_in, const int* in_sizes, int n_in,
                              void* d_out, int out_size) {
    const float* x        = (const float*)d_in[0];
    const float* rel_type = (const float*)d_in[1];
    // d_in[2]=rel_rec, d_in[3]=rel_send: structure is analytic, unused
    const float* w1  = (const float*)d_in[4];
    const float* b1  = (const float*)d_in[5];
    const float* w2  = (const float*)d_in[6];
    const float* b2  = (const float*)d_in[7];
    const float* ow1 = (const float*)d_in[8];
    const float* ob1 = (const float*)d_in[9];
    const float* ow2 = (const float*)d_in[10];
    const float* ob2 = (const float*)d_in[11];
    const float* ow3 = (const float*)d_in[12];
    const float* ob3 = (const float*)d_in[13];
    float* out = (float*)d_out;

    cudaFuncSetAttribute(k2_edge, cudaFuncAttributeMaxDynamicSharedMemorySize, K2_SMEM);

    k1_proj<<<dim3(16, 64), 256>>>(x, w1, b1);
    k2_edge<<<dim3(16, 64), 256, K2_SMEM>>>(rel_type, w2, b2);
    k3_out<<<256, 256>>>(x, ow1, ob1, ow2, ob2, ow3, ob3, out);
}

// round 8
// speedup vs baseline: 6.0441x; 1.0030x over previous
#include <cuda_runtime.h>
#include <cuda_fp16.h>

// Shapes (fixed by the problem)
#define B_   64
#define N_   64
#define FIN  64
#define HID  256
#define OUT  64
#define T_   4
#define E_   4032   // N*(N-1)

typedef unsigned int u32;

// Scratch (device globals: no allocation allowed)
__device__ __half g_Pa[T_ * B_ * N_ * HID];   // x @ w1[:, :64, :]          (8 MB)
__device__ __half g_Pb[T_ * B_ * N_ * HID];   // x @ w1[:, 64:, :] + b1     (8 MB)
__device__ float  g_agg[B_ * N_ * OUT];       // edge2node aggregate        (1 MB)

// ---------------- fp16 mma helper ----------------
__device__ __forceinline__ void mma_f16(float c[4], const u32 a[4], const u32 b[2]) {
    asm volatile(
        "mma.sync.aligned.m16n8k16.row.col.f32.f16.f16.f32 "
        "{%0,%1,%2,%3},{%4,%5,%6,%7},{%8,%9},{%0,%1,%2,%3};"
        : "+f"(c[0]), "+f"(c[1]), "+f"(c[2]), "+f"(c[3])
        : "r"(a[0]), "r"(a[1]), "r"(a[2]), "r"(a[3]), "r"(b[0]), "r"(b[1]));
}

// ---------------------------------------------------------------------------
// K1: node projections.  X[4096,64] @ W_all[64,2048]; cols = (t, part, h).
// part=0 -> Pa (w1[t][k][h]); part=1 -> Pb (w1[t][64+k][h] + b1). fp16 out.
// ---------------------------------------------------------------------------
__global__ void __launch_bounds__(256) k1_proj(const float* __restrict__ x,
                                               const float* __restrict__ w1,
                                               const float* __restrict__ b1) {
    __shared__ float sX[64 * 64];
    __shared__ float sW[64 * 128];
    const int tid = threadIdx.x;
    const int rb = blockIdx.y, cb = blockIdx.x;

#pragma unroll
    for (int i = 0; i < 16; i++)
        sX[tid + i * 256] = x[rb * 4096 + tid + i * 256];

    const int colbase = cb * 128;
#pragma unroll
    for (int i = 0; i < 32; i++) {
        int idx = tid + i * 256;
        int k = idx >> 7, c = idx & 127;
        int col = colbase + c;
        int t = col >> 9, part = (col >> 8) & 1, h = col & 255;
        sW[idx] = w1[t * 32768 + (part * 64 + k) * 256 + h];
    }
    __syncthreads();

    const int to = tid & 31, tr = tid >> 5;
    float acc[8][4];
#pragma unroll
    for (int r = 0; r < 8; r++)
#pragma unroll
        for (int j = 0; j < 4; j++) acc[r][j] = 0.f;

#pragma unroll 4
    for (int k = 0; k < 64; k++) {
        float4 w = *(const float4*)(sW + k * 128 + to * 4);
        float a[8];
#pragma unroll
        for (int r = 0; r < 8; r++) a[r] = sX[(tr * 8 + r) * 64 + k];
#pragma unroll
        for (int r = 0; r < 8; r++) {
            acc[r][0] += a[r] * w.x;
            acc[r][1] += a[r] * w.y;
            acc[r][2] += a[r] * w.z;
            acc[r][3] += a[r] * w.w;
        }
    }

    const int col0 = colbase + to * 4;
    const int t = col0 >> 9, part = (col0 >> 8) & 1, h = col0 & 255;
    float4 bias = make_float4(0.f, 0.f, 0.f, 0.f);
    if (part) {
        bias.x = b1[t * 256 + h + 0];
        bias.y = b1[t * 256 + h + 1];
        bias.z = b1[t * 256 + h + 2];
        bias.w = b1[t * 256 + h + 3];
    }
    __half* dst = (part ? g_Pb : g_Pa) + ((t * 4096 + rb * 64 + tr * 8) * 256 + h);
#pragma unroll
    for (int r = 0; r < 8; r++) {
        __half2 h01 = __floats2half2_rn(acc[r][0] + bias.x, acc[r][1] + bias.y);
        __half2 h23 = __floats2half2_rn(acc[r][2] + bias.z, acc[r][3] + bias.w);
        uint2 v;
        v.x = *(u32*)&h01;
        v.y = *(u32*)&h23;
        *(uint2*)(dst + r * 256) = v;
    }
}

// ---------------------------------------------------------------------------
// K2 (dominant, fp16 tensor-core): block = (b, 4 receivers), loops t(4).
// sA [row=256(4 recv x 64 send)][k=256, pad 264] half = relu(Pa[s]+Pb[r]).
// sB [k=256][o=64, pad 72] half = w2[t].
// Warp (r_local = wid&3, nhalf = wid>>2): 64M x 32N x 256K via ldmatrix +
// mma.m16n8k16.f16.f32. Epilogue: relu(C+b2)*rel_type, shuffle-reduce over
// senders, accumulate in registers across t; one plain float2 store / lane.
// ---------------------------------------------------------------------------
#define SA_K 264
#define SB_O 72
#define K2_SMEM (256 * SA_K * 2 + 256 * SB_O * 2 + 256 * 4 + 64 * 4)

__global__ void __launch_bounds__(256) k2_edge(const float* __restrict__ rel_type,
                                               const float* __restrict__ w2,
                                               const float* __restrict__ b2) {
    extern __shared__ __align__(16) char smraw[];
    __half* sA = (__half*)smraw;                              // [256][SA_K]
    __half* sB = (__half*)(smraw + 256 * SA_K * 2);           // [256][SB_O]
    float* rt_sm = (float*)(smraw + 256 * SA_K * 2 + 256 * SB_O * 2);  // [4][64]
    float* b2s = rt_sm + 256;                                 // [64]

    const int tid = threadIdx.x;
    const int lane = tid & 31, wid = tid >> 5;
    const int b = blockIdx.y, rbase = blockIdx.x * 4;
    const int r_local = wid & 3;      // receiver owned by this warp
    const int nhalf = wid >> 2;       // which 32-col half of the 64 outputs
    const int g4 = lane >> 2, t4 = lane & 3;

    const u32 sA_u = (u32)__cvta_generic_to_shared(sA);
    const u32 sB_u = (u32)__cvta_generic_to_shared(sB);

    // ldmatrix lane address bases
    // A x4: m0 rows0-7/k0, m1 rows8-15/k0, m2 rows0-7/k8, m3 rows8-15/k8
    const u32 aAddr = sA_u +
        (u32)(((r_local * 64 + (lane & 7) + ((lane >> 3) & 1) * 8) * SA_K +
               (lane >> 4) * 8) * 2);
    // B x2.trans: lanes 0-15 -> rows k+0..15 (cols = nhalf*32 base)
    const u32 bAddr = sB_u + (u32)(((lane & 15) * SB_O + nhalf * 32) * 2);

    float racc[4][2];
#pragma unroll
    for (int nt = 0; nt < 4; nt++) { racc[nt][0] = 0.f; racc[nt][1] = 0.f; }

    const __half2 z2 = __float2half2_rn(0.f);

    for (int t = 0; t < 4; t++) {
        __syncthreads();   // previous iteration's mma/epilogue done

        // ---- stage sB = fp16(w2[t]) as [k][o] ----
        const float4* w2t4 = (const float4*)(w2 + t * 16384);
#pragma unroll
        for (int i = 0; i < 16; i++) {
            int idx = i * 256 + tid;            // 4096 float4
            int k = idx >> 4, o4 = idx & 15;
            float4 w = w2t4[idx];
            __half2 h01 = __floats2half2_rn(w.x, w.y);
            __half2 h23 = __floats2half2_rn(w.z, w.w);
            __half2* dst = (__half2*)(sB + k * SB_O + o4 * 4);
            dst[0] = h01;
            dst[1] = h23;
        }
        // ---- stage rel_type for 4 receivers x 64 senders ----
        {
            int s = tid & 63, rl = tid >> 6;
            int r = rbase + rl;
            float v = 0.f;
            if (s != r) v = rel_type[(b * 4032 + s * 63 + r - (r > s ? 1 : 0)) * 4 + t];
            rt_sm[rl * 64 + s] = v;
        }
        if (tid < 64) b2s[tid] = b2[t * 64 + tid];

        // ---- build sA: row = rl*64+s, relu(Pa[s] + Pb[rbase+rl]) in fp16 ----
        const __half* PaH = g_Pa + (t * 4096 + b * 64) * 256;
        const __half* PbH = g_Pb + (t * 4096 + b * 64) * 256;
#pragma unroll
        for (int i = 0; i < 32; i++) {
            int grp = i * 256 + tid;            // 8192 groups of 8 halves
            int row = grp >> 5, c8 = grp & 31;
            int s = row & 63, rl = row >> 6;
            uint4 pa = *(const uint4*)(PaH + s * 256 + c8 * 8);
            uint4 pb = *(const uint4*)(PbH + (rbase + rl) * 256 + c8 * 8);
            uint4 o;
            __half2 v;
            v = __hmax2(__hadd2(*(__half2*)&pa.x, *(__half2*)&pb.x), z2); o.x = *(u32*)&v;
            v = __hmax2(__hadd2(*(__half2*)&pa.y, *(__half2*)&pb.y), z2); o.y = *(u32*)&v;
            v = __hmax2(__hadd2(*(__half2*)&pa.z, *(__half2*)&pb.z), z2); o.z = *(u32*)&v;
            v = __hmax2(__hadd2(*(__half2*)&pa.w, *(__half2*)&pb.w), z2); o.w = *(u32*)&v;
            *(uint4*)(sA + row * SA_K + c8 * 8) = o;
        }
        __syncthreads();

        // ---- 64x32x256 warp GEMM: 4mt x 4nt m16n8k16 tiles, 16 k-chunks ----
        float c[16][4];
#pragma unroll
        for (int i = 0; i < 16; i++)
#pragma unroll
            for (int j = 0; j < 4; j++) c[i][j] = 0.f;

#pragma unroll
        for (int kc = 0; kc < 16; kc++) {
            u32 bf[4][2];
#pragma unroll
            for (int nt = 0; nt < 4; nt++) {
                u32 addr = bAddr + (u32)((kc * 16 * SB_O + nt * 8) * 2);
                asm volatile(
                    "ldmatrix.sync.aligned.m8n8.x2.trans.shared.b16 {%0,%1}, [%2];"
                    : "=r"(bf[nt][0]), "=r"(bf[nt][1]) : "r"(addr));
            }
#pragma unroll
            for (int mt = 0; mt < 4; mt++) {
                u32 a[4];
                u32 addr = aAddr + (u32)((mt * 16 * SA_K + kc * 16) * 2);
                asm volatile(
                    "ldmatrix.sync.aligned.m8n8.x4.shared.b16 {%0,%1,%2,%3}, [%4];"
                    : "=r"(a[0]), "=r"(a[1]), "=r"(a[2]), "=r"(a[3]) : "r"(addr));
#pragma unroll
                for (int nt = 0; nt < 4; nt++)
                    mma_f16(c[mt * 4 + nt], a, bf[nt]);
            }
        }

        // ---- epilogue: relu(C + b2)*rt, reduce over senders, accum in regs ----
        float rtv[4][2];
#pragma unroll
        for (int mt = 0; mt < 4; mt++) {
            rtv[mt][0] = rt_sm[r_local * 64 + mt * 16 + g4];
            rtv[mt][1] = rt_sm[r_local * 64 + mt * 16 + g4 + 8];
        }
#pragma unroll
        for (int nt = 0; nt < 4; nt++) {
            int col = nhalf * 32 + nt * 8 + 2 * t4;
            float bb0 = b2s[col], bb1 = b2s[col + 1];
            float p0 = 0.f, p1 = 0.f;
#pragma unroll
            for (int mt = 0; mt < 4; mt++) {
                const float* cc = c[mt * 4 + nt];
                p0 += fmaxf(cc[0] + bb0, 0.f) * rtv[mt][0];
                p1 += fmaxf(cc[1] + bb1, 0.f) * rtv[mt][0];
                p0 += fmaxf(cc[2] + bb0, 0.f) * rtv[mt][1];
                p1 += fmaxf(cc[3] + bb1, 0.f) * rtv[mt][1];
            }
#pragma unroll
            for (int off = 4; off < 32; off <<= 1) {
                p0 += __shfl_xor_sync(0xffffffffu, p0, off);
                p1 += __shfl_xor_sync(0xffffffffu, p1, off);
            }
            racc[nt][0] += p0;
            racc[nt][1] += p1;
        }
    }

    // ---- final store: each (b, r, col) owned by exactly one warp ----
    if (lane < 4) {   // g4 == 0 lanes, t4 = lane
        float* dst = g_agg + (b * 64 + rbase + r_local) * 64 + nhalf * 32 + 2 * t4;
#pragma unroll
        for (int nt = 0; nt < 4; nt++)
            *(float2*)(dst + nt * 8) = make_float2(racc[nt][0], racc[nt][1]);
    }
}

// ---------------------------------------------------------------------------
// K3: output MLP, float4 weight loads, 4 cols x 4 rows per thread.
// grid = 256 blocks x 16 rows, 256 threads.
// ---------------------------------------------------------------------------
__global__ void __launch_bounds__(256) k3_out(const float* __restrict__ x,
                                              const float* __restrict__ ow1,
                                              const float* __restrict__ ob1,
                                              const float* __restrict__ ow2,
                                              const float* __restrict__ ob2,
                                              const float* __restrict__ ow3,
                                              const float* __restrict__ ob3,
                                              float* __restrict__ out) {
    __shared__ float sAug[16 * 128];
    __shared__ float4 sH[16 * 64];
    __shared__ float4 sH2[16 * 64];
    const int tid = threadIdx.x;
    const int base = blockIdx.x * 16;

#pragma unroll
    for (int i = 0; i < 8; i++) {
        int idx = tid + i * 256;
        int row = idx >> 7, c = idx & 127;
        float v = (c < 64) ? x[(base + row) * 64 + c]
                           : g_agg[(base + row) * 64 + (c - 64)];
        sAug[idx] = v;
    }
    __syncthreads();

    const int cg = tid & 63, rg = tid >> 6;
    const float* sHf = (const float*)sH;
    const float* sH2f = (const float*)sH2;

    {   // stage 1: 128 -> 256
        float acc[4][4];
#pragma unroll
        for (int r = 0; r < 4; r++)
#pragma unroll
            for (int j = 0; j < 4; j++) acc[r][j] = 0.f;
#pragma unroll 4
        for (int k = 0; k < 128; k++) {
            float4 w = *((const float4*)(ow1 + k * 256) + cg);
#pragma unroll
            for (int r = 0; r < 4; r++) {
                float a = sAug[(rg * 4 + r) * 128 + k];
                acc[r][0] += a * w.x; acc[r][1] += a * w.y;
                acc[r][2] += a * w.z; acc[r][3] += a * w.w;
            }
        }
        float4 bb = *((const float4*)ob1 + cg);
#pragma unroll
        for (int r = 0; r < 4; r++)
            sH[(rg * 4 + r) * 64 + cg] = make_float4(
                fmaxf(acc[r][0] + bb.x, 0.f), fmaxf(acc[r][1] + bb.y, 0.f),
                fmaxf(acc[r][2] + bb.z, 0.f), fmaxf(acc[r][3] + bb.w, 0.f));
    }
    __syncthreads();

    {   // stage 2: 256 -> 256
        float acc[4][4];
#pragma unroll
        for (int r = 0; r < 4; r++)
#pragma unroll
            for (int j = 0; j < 4; j++) acc[r][j] = 0.f;
#pragma unroll 4
        for (int k = 0; k < 256; k++) {
            float4 w = *((const float4*)(ow2 + k * 256) + cg);
#pragma unroll
            for (int r = 0; r < 4; r++) {
                float a = sHf[(rg * 4 + r) * 256 + k];
                acc[r][0] += a * w.x; acc[r][1] += a * w.y;
                acc[r][2] += a * w.z; acc[r][3] += a * w.w;
            }
        }
        float4 bb = *((const float4*)ob2 + cg);
#pragma unroll
        for (int r = 0; r < 4; r++)
            sH2[(rg * 4 + r) * 64 + cg] = make_float4(
                fmaxf(acc[r][0] + bb.x, 0.f), fmaxf(acc[r][1] + bb.y, 0.f),
                fmaxf(acc[r][2] + bb.z, 0.f), fmaxf(acc[r][3] + bb.w, 0.f));
    }
    __syncthreads();

    {   // stage 3: 256 -> 64
        const int cg2 = tid & 15, rg2 = tid >> 4;
        float a0 = 0.f, a1 = 0.f, a2 = 0.f, a3 = 0.f;
#pragma unroll 4
        for (int k = 0; k < 256; k++) {
            float4 w = *((const float4*)(ow3 + k * 64) + cg2);
            float a = sH2f[rg2 * 256 + k];
            a0 += a * w.x; a1 += a * w.y; a2 += a * w.z; a3 += a * w.w;
        }
        float4 bb = *((const float4*)ob3 + cg2);
        float4 v = make_float4(a0 + bb.x, a1 + bb.y, a2 + bb.z, a3 + bb.w);
        *((float4*)(out + (base + rg2) * 64) + cg2) = v;
    }
}

// ---------------------------------------------------------------------------
extern "C" void kernel_launch(void* const* d_in, const int* in_sizes, int n_in,
                              void* d_out, int out_size) {
    const float* x        = (const float*)d_in[0];
    const float* rel_type = (const float*)d_in[1];
    // d_in[2]=rel_rec, d_in[3]=rel_send: structure is analytic, unused
    const float* w1  = (const float*)d_in[4];
    const float* b1  = (const float*)d_in[5];
    const float* w2  = (const float*)d_in[6];
    const float* b2  = (const float*)d_in[7];
    const float* ow1 = (const float*)d_in[8];
    const float* ob1 = (const float*)d_in[9];
    const float* ow2 = (const float*)d_in[10];
    const float* ob2 = (const float*)d_in[11];
    const float* ow3 = (const float*)d_in[12];
    const float* ob3 = (const float*)d_in[13];
    float* out = (float*)d_out;

    cudaFuncSetAttribute(k2_edge, cudaFuncAttributeMaxDynamicSharedMemorySize, K2_SMEM);

    k1_proj<<<dim3(16, 64), 256>>>(x, w1, b1);
    k2_edge<<<dim3(16, 64), 256, K2_SMEM>>>(rel_type, w2, b2);
    k3_out<<<256, 256>>>(x, ow1, ob1, ow2, ob2, ow3, ob3, out);
}

// round 9
// speedup vs baseline: 6.0496x; 1.0009x over previous
#include <cuda_runtime.h>
#include <cuda_fp16.h>

// Shapes (fixed by the problem)
#define B_   64
#define N_   64
#define FIN  64
#define HID  256
#define OUT  64
#define T_   4
#define E_   4032   // N*(N-1)

typedef unsigned int u32;

// Scratch (device globals: no allocation allowed)
__device__ __half g_Pa[T_ * B_ * N_ * HID];   // x @ w1[:, :64, :]          (8 MB)
__device__ __half g_Pb[T_ * B_ * N_ * HID];   // x @ w1[:, 64:, :] + b1     (8 MB)
__device__ float  g_agg[B_ * N_ * OUT];       // edge2node aggregate        (1 MB)

// ---------------- fp16 mma helper ----------------
__device__ __forceinline__ void mma_f16(float c[4], const u32 a[4], const u32 b[2]) {
    asm volatile(
        "mma.sync.aligned.m16n8k16.row.col.f32.f16.f16.f32 "
        "{%0,%1,%2,%3},{%4,%5,%6,%7},{%8,%9},{%0,%1,%2,%3};"
        : "+f"(c[0]), "+f"(c[1]), "+f"(c[2]), "+f"(c[3])
        : "r"(a[0]), "r"(a[1]), "r"(a[2]), "r"(a[3]), "r"(b[0]), "r"(b[1]));
}

// ---------------------------------------------------------------------------
// K1: node projections.  X[4096,64] @ W_all[64,2048]; cols = (t, part, h).
// part=0 -> Pa (w1[t][k][h]); part=1 -> Pb (w1[t][64+k][h] + b1). fp16 out.
// ---------------------------------------------------------------------------
__global__ void __launch_bounds__(256) k1_proj(const float* __restrict__ x,
                                               const float* __restrict__ w1,
                                               const float* __restrict__ b1) {
    __shared__ float sX[64 * 64];
    __shared__ float sW[64 * 128];
    const int tid = threadIdx.x;
    const int rb = blockIdx.y, cb = blockIdx.x;

#pragma unroll
    for (int i = 0; i < 16; i++)
        sX[tid + i * 256] = x[rb * 4096 + tid + i * 256];

    const int colbase = cb * 128;
#pragma unroll
    for (int i = 0; i < 32; i++) {
        int idx = tid + i * 256;
        int k = idx >> 7, c = idx & 127;
        int col = colbase + c;
        int t = col >> 9, part = (col >> 8) & 1, h = col & 255;
        sW[idx] = w1[t * 32768 + (part * 64 + k) * 256 + h];
    }
    __syncthreads();

    const int to = tid & 31, tr = tid >> 5;
    float acc[8][4];
#pragma unroll
    for (int r = 0; r < 8; r++)
#pragma unroll
        for (int j = 0; j < 4; j++) acc[r][j] = 0.f;

#pragma unroll 4
    for (int k = 0; k < 64; k++) {
        float4 w = *(const float4*)(sW + k * 128 + to * 4);
        float a[8];
#pragma unroll
        for (int r = 0; r < 8; r++) a[r] = sX[(tr * 8 + r) * 64 + k];
#pragma unroll
        for (int r = 0; r < 8; r++) {
            acc[r][0] += a[r] * w.x;
            acc[r][1] += a[r] * w.y;
            acc[r][2] += a[r] * w.z;
            acc[r][3] += a[r] * w.w;
        }
    }

    const int col0 = colbase + to * 4;
    const int t = col0 >> 9, part = (col0 >> 8) & 1, h = col0 & 255;
    float4 bias = make_float4(0.f, 0.f, 0.f, 0.f);
    if (part) {
        bias.x = b1[t * 256 + h + 0];
        bias.y = b1[t * 256 + h + 1];
        bias.z = b1[t * 256 + h + 2];
        bias.w = b1[t * 256 + h + 3];
    }
    __half* dst = (part ? g_Pb : g_Pa) + ((t * 4096 + rb * 64 + tr * 8) * 256 + h);
#pragma unroll
    for (int r = 0; r < 8; r++) {
        __half2 h01 = __floats2half2_rn(acc[r][0] + bias.x, acc[r][1] + bias.y);
        __half2 h23 = __floats2half2_rn(acc[r][2] + bias.z, acc[r][3] + bias.w);
        uint2 v;
        v.x = *(u32*)&h01;
        v.y = *(u32*)&h23;
        *(uint2*)(dst + r * 256) = v;
    }
}

// ---------------------------------------------------------------------------
// K2 (dominant, fp16 tensor-core): block = (b, 4 receivers), loops t(4).
// sA [row=256(4 recv x 64 send)][k=256, pad 264] half = relu(Pa[s]+Pb[r]).
// sB [k=256][o=64, pad 72] half = w2[t].
// Warp (r_local = wid&3, nhalf = wid>>2): 64M x 32N x 256K via ldmatrix +
// mma.m16n8k16.f16.f32. Epilogue: relu(C+b2)*rel_type, shuffle-reduce over
// senders, accumulate in registers across t; one plain float2 store / lane.
// ---------------------------------------------------------------------------
#define SA_K 264
#define SB_O 72
#define K2_SMEM (256 * SA_K * 2 + 256 * SB_O * 2 + 256 * 4 + 64 * 4)

__global__ void __launch_bounds__(256) k2_edge(const float* __restrict__ rel_type,
                                               const float* __restrict__ w2,
                                               const float* __restrict__ b2) {
    extern __shared__ __align__(16) char smraw[];
    __half* sA = (__half*)smraw;                              // [256][SA_K]
    __half* sB = (__half*)(smraw + 256 * SA_K * 2);           // [256][SB_O]
    float* rt_sm = (float*)(smraw + 256 * SA_K * 2 + 256 * SB_O * 2);  // [4][64]
    float* b2s = rt_sm + 256;                                 // [64]

    const int tid = threadIdx.x;
    const int lane = tid & 31, wid = tid >> 5;
    const int b = blockIdx.y, rbase = blockIdx.x * 4;
    const int r_local = wid & 3;      // receiver owned by this warp
    const int nhalf = wid >> 2;       // which 32-col half of the 64 outputs
    const int g4 = lane >> 2, t4 = lane & 3;

    const u32 sA_u = (u32)__cvta_generic_to_shared(sA);
    const u32 sB_u = (u32)__cvta_generic_to_shared(sB);

    // ldmatrix lane address bases
    // A x4: m0 rows0-7/k0, m1 rows8-15/k0, m2 rows0-7/k8, m3 rows8-15/k8
    const u32 aAddr = sA_u +
        (u32)(((r_local * 64 + (lane & 7) + ((lane >> 3) & 1) * 8) * SA_K +
               (lane >> 4) * 8) * 2);
    // B x2.trans: lanes 0-15 -> rows k+0..15 (cols = nhalf*32 base)
    const u32 bAddr = sB_u + (u32)(((lane & 15) * SB_O + nhalf * 32) * 2);

    float racc[4][2];
#pragma unroll
    for (int nt = 0; nt < 4; nt++) { racc[nt][0] = 0.f; racc[nt][1] = 0.f; }

    const __half2 z2 = __float2half2_rn(0.f);

    for (int t = 0; t < 4; t++) {
        __syncthreads();   // previous iteration's mma/epilogue done

        // ---- stage sB = fp16(w2[t]) as [k][o] ----
        const float4* w2t4 = (const float4*)(w2 + t * 16384);
#pragma unroll
        for (int i = 0; i < 16; i++) {
            int idx = i * 256 + tid;            // 4096 float4
            int k = idx >> 4, o4 = idx & 15;
            float4 w = w2t4[idx];
            __half2 h01 = __floats2half2_rn(w.x, w.y);
            __half2 h23 = __floats2half2_rn(w.z, w.w);
            __half2* dst = (__half2*)(sB + k * SB_O + o4 * 4);
            dst[0] = h01;
            dst[1] = h23;
        }
        // ---- stage rel_type for 4 receivers x 64 senders ----
        {
            int s = tid & 63, rl = tid >> 6;
            int r = rbase + rl;
            float v = 0.f;
            if (s != r) v = rel_type[(b * 4032 + s * 63 + r - (r > s ? 1 : 0)) * 4 + t];
            rt_sm[rl * 64 + s] = v;
        }
        if (tid < 64) b2s[tid] = b2[t * 64 + tid];

        // ---- build sA: row = rl*64+s, relu(Pa[s] + Pb[rbase+rl]) in fp16 ----
        const __half* PaH = g_Pa + (t * 4096 + b * 64) * 256;
        const __half* PbH = g_Pb + (t * 4096 + b * 64) * 256;
#pragma unroll
        for (int i = 0; i < 32; i++) {
            int grp = i * 256 + tid;            // 8192 groups of 8 halves
            int row = grp >> 5, c8 = grp & 31;
            int s = row & 63, rl = row >> 6;
            uint4 pa = *(const uint4*)(PaH + s * 256 + c8 * 8);
            uint4 pb = *(const uint4*)(PbH + (rbase + rl) * 256 + c8 * 8);
            uint4 o;
            __half2 v;
            v = __hmax2(__hadd2(*(__half2*)&pa.x, *(__half2*)&pb.x), z2); o.x = *(u32*)&v;
            v = __hmax2(__hadd2(*(__half2*)&pa.y, *(__half2*)&pb.y), z2); o.y = *(u32*)&v;
            v = __hmax2(__hadd2(*(__half2*)&pa.z, *(__half2*)&pb.z), z2); o.z = *(u32*)&v;
            v = __hmax2(__hadd2(*(__half2*)&pa.w, *(__half2*)&pb.w), z2); o.w = *(u32*)&v;
            *(uint4*)(sA + row * SA_K + c8 * 8) = o;
        }
        __syncthreads();

        // ---- 64x32x256 warp GEMM: 4mt x 4nt m16n8k16 tiles, 16 k-chunks ----
        float c[16][4];
#pragma unroll
        for (int i = 0; i < 16; i++)
#pragma unroll
            for (int j = 0; j < 4; j++) c[i][j] = 0.f;

#pragma unroll
        for (int kc = 0; kc < 16; kc++) {
            u32 bf[4][2];
#pragma unroll
            for (int nt = 0; nt < 4; nt++) {
                u32 addr = bAddr + (u32)((kc * 16 * SB_O + nt * 8) * 2);
                asm volatile(
                    "ldmatrix.sync.aligned.m8n8.x2.trans.shared.b16 {%0,%1}, [%2];"
                    : "=r"(bf[nt][0]), "=r"(bf[nt][1]) : "r"(addr));
            }
#pragma unroll
            for (int mt = 0; mt < 4; mt++) {
                u32 a[4];
                u32 addr = aAddr + (u32)((mt * 16 * SA_K + kc * 16) * 2);
                asm volatile(
                    "ldmatrix.sync.aligned.m8n8.x4.shared.b16 {%0,%1,%2,%3}, [%4];"
                    : "=r"(a[0]), "=r"(a[1]), "=r"(a[2]), "=r"(a[3]) : "r"(addr));
#pragma unroll
                for (int nt = 0; nt < 4; nt++)
                    mma_f16(c[mt * 4 + nt], a, bf[nt]);
            }
        }

        // ---- epilogue: relu(C + b2)*rt, reduce over senders, accum in regs ----
        float rtv[4][2];
#pragma unroll
        for (int mt = 0; mt < 4; mt++) {
            rtv[mt][0] = rt_sm[r_local * 64 + mt * 16 + g4];
            rtv[mt][1] = rt_sm[r_local * 64 + mt * 16 + g4 + 8];
        }
#pragma unroll
        for (int nt = 0; nt < 4; nt++) {
            int col = nhalf * 32 + nt * 8 + 2 * t4;
            float bb0 = b2s[col], bb1 = b2s[col + 1];
            float p0 = 0.f, p1 = 0.f;
#pragma unroll
            for (int mt = 0; mt < 4; mt++) {
                const float* cc = c[mt * 4 + nt];
                p0 += fmaxf(cc[0] + bb0, 0.f) * rtv[mt][0];
                p1 += fmaxf(cc[1] + bb1, 0.f) * rtv[mt][0];
                p0 += fmaxf(cc[2] + bb0, 0.f) * rtv[mt][1];
                p1 += fmaxf(cc[3] + bb1, 0.f) * rtv[mt][1];
            }
#pragma unroll
            for (int off = 4; off < 32; off <<= 1) {
                p0 += __shfl_xor_sync(0xffffffffu, p0, off);
                p1 += __shfl_xor_sync(0xffffffffu, p1, off);
            }
            racc[nt][0] += p0;
            racc[nt][1] += p1;
        }
    }

    // ---- final store: each (b, r, col) owned by exactly one warp ----
    if (lane < 4) {   // g4 == 0 lanes, t4 = lane
        float* dst = g_agg + (b * 64 + rbase + r_local) * 64 + nhalf * 32 + 2 * t4;
#pragma unroll
        for (int nt = 0; nt < 4; nt++)
            *(float2*)(dst + nt * 8) = make_float2(racc[nt][0], racc[nt][1]);
    }
}

// ---------------------------------------------------------------------------
// K3: output MLP, float4 weight loads, 4 cols x 4 rows per thread.
// grid = 256 blocks x 16 rows, 256 threads.
// ---------------------------------------------------------------------------
__global__ void __launch_bounds__(256) k3_out(const float* __restrict__ x,
                                              const float* __restrict__ ow1,
                                              const float* __restrict__ ob1,
                                              const float* __restrict__ ow2,
                                              const float* __restrict__ ob2,
                                              const float* __restrict__ ow3,
                                              const float* __restrict__ ob3,
                                              float* __restrict__ out) {
    __shared__ float sAug[16 * 128];
    __shared__ float4 sH[16 * 64];
    __shared__ float4 sH2[16 * 64];
    const int tid = threadIdx.x;
    const int base = blockIdx.x * 16;

#pragma unroll
    for (int i = 0; i < 8; i++) {
        int idx = tid + i * 256;
        int row = idx >> 7, c = idx & 127;
        float v = (c < 64) ? x[(base + row) * 64 + c]
                           : g_agg[(base + row) * 64 + (c - 64)];
        sAug[idx] = v;
    }
    __syncthreads();

    const int cg = tid & 63, rg = tid >> 6;
    const float* sHf = (const float*)sH;
    const float* sH2f = (const float*)sH2;

    {   // stage 1: 128 -> 256
        float acc[4][4];
#pragma unroll
        for (int r = 0; r < 4; r++)
#pragma unroll
            for (int j = 0; j < 4; j++) acc[r][j] = 0.f;
#pragma unroll 4
        for (int k = 0; k < 128; k++) {
            float4 w = *((const float4*)(ow1 + k * 256) + cg);
#pragma unroll
            for (int r = 0; r < 4; r++) {
                float a = sAug[(rg * 4 + r) * 128 + k];
                acc[r][0] += a * w.x; acc[r][1] += a * w.y;
                acc[r][2] += a * w.z; acc[r][3] += a * w.w;
            }
        }
        float4 bb = *((const float4*)ob1 + cg);
#pragma unroll
        for (int r = 0; r < 4; r++)
            sH[(rg * 4 + r) * 64 + cg] = make_float4(
                fmaxf(acc[r][0] + bb.x, 0.f), fmaxf(acc[r][1] + bb.y, 0.f),
                fmaxf(acc[r][2] + bb.z, 0.f), fmaxf(acc[r][3] + bb.w, 0.f));
    }
    __syncthreads();

    {   // stage 2: 256 -> 256
        float acc[4][4];
#pragma unroll
        for (int r = 0; r < 4; r++)
#pragma unroll
            for (int j = 0; j < 4; j++) acc[r][j] = 0.f;
#pragma unroll 4
        for (int k = 0; k < 256; k++) {
            float4 w = *((const float4*)(ow2 + k * 256) + cg);
#pragma unroll
            for (int r = 0; r < 4; r++) {
                float a = sHf[(rg * 4 + r) * 256 + k];
                acc[r][0] += a * w.x; acc[r][1] += a * w.y;
                acc[r][2] += a * w.z; acc[r][3] += a * w.w;
            }
        }
        float4 bb = *((const float4*)ob2 + cg);
#pragma unroll
        for (int r = 0; r < 4; r++)
            sH2[(rg * 4 + r) * 64 + cg] = make_float4(
                fmaxf(acc[r][0] + bb.x, 0.f), fmaxf(acc[r][1] + bb.y, 0.f),
                fmaxf(acc[r][2] + bb.z, 0.f), fmaxf(acc[r][3] + bb.w, 0.f));
    }
    __syncthreads();

    {   // stage 3: 256 -> 64
        const int cg2 = tid & 15, rg2 = tid >> 4;
        float a0 = 0.f, a1 = 0.f, a2 = 0.f, a3 = 0.f;
#pragma unroll 4
        for (int k = 0; k < 256; k++) {
            float4 w = *((const float4*)(ow3 + k * 64) + cg2);
            float a = sH2f[rg2 * 256 + k];
            a0 += a * w.x; a1 += a * w.y; a2 += a * w.z; a3 += a * w.w;
        }
        float4 bb = *((const float4*)ob3 + cg2);
        float4 v = make_float4(a0 + bb.x, a1 + bb.y, a2 + bb.z, a3 + bb.w);
        *((float4*)(out + (base + rg2) * 64) + cg2) = v;
    }
}

// ---------------------------------------------------------------------------
extern "C" void kernel_launch(void* const* d_in, const int* in_sizes, int n_in,
                              void* d_out, int out_size) {
    const float* x        = (const float*)d_in[0];
    const float* rel_type = (const float*)d_in[1];
    // d_in[2]=rel_rec, d_in[3]=rel_send: structure is analytic, unused
    const float* w1  = (const float*)d_in[4];
    const float* b1  = (const float*)d_in[5];
    const float* w2  = (const float*)d_in[6];
    const float* b2  = (const float*)d_in[7];
    const float* ow1 = (const float*)d_in[8];
    const float* ob1 = (const float*)d_in[9];
    const float* ow2 = (const float*)d_in[10];
    const float* ob2 = (const float*)d_in[11];
    const float* ow3 = (const float*)d_in[12];
    const float* ob3 = (const float*)d_in[13];
    float* out = (float*)d_out;

    cudaFuncSetAttribute(k2_edge, cudaFuncAttributeMaxDynamicSharedMemorySize, K2_SMEM);

    k1_proj<<<dim3(16, 64), 256>>>(x, w1, b1);
    k2_edge<<<dim3(16, 64), 256, K2_SMEM>>>(rel_type, w2, b2);
    k3_out<<<256, 256>>>(x, ow1, ob1, ow2, ob2, ow3, ob3, out);
}